// round 12
// baseline (speedup 1.0000x reference)
#include <cuda_runtime.h>
#include <cuda_bf16.h>
#include <cstdint>

#define NH    12
#define HD    64
#define SEQ   1025
#define BATCH 8
#define DIM   768
#define M_ROWS (BATCH * SEQ)   /* 8200 */
#define BHN   (BATCH * NH)     /* 96 */
#define NKP   1152             /* keys padded to 9*128 */
#define SROW2 72               /* padded smem row (bf16) for 64-dim tiles */
#define SROW  40               /* padded smem row (bf16) for 32-wide k-chunks */

// ---------------- scratch (device globals: allocation-free) ----------------
__device__ float g_v[(size_t)M_ROWS * DIM];    // v only (k eliminated algebraically)

__device__ __nv_bfloat16 g_x_hi[(size_t)M_ROWS * DIM];
__device__ __nv_bfloat16 g_x_lo[(size_t)M_ROWS * DIM];
__device__ __nv_bfloat16 g_wv_hi[(size_t)DIM * DIM];
__device__ __nv_bfloat16 g_wv_lo[(size_t)DIM * DIM];
__device__ __nv_bfloat16 g_o_hi[(size_t)M_ROWS * DIM];
__device__ __nv_bfloat16 g_o_lo[(size_t)M_ROWS * DIM];
__device__ __nv_bfloat16 g_wp_hi[(size_t)DIM * DIM];
__device__ __nv_bfloat16 g_wp_lo[(size_t)DIM * DIM];

// VV attention operands: [bh][1152][64] bf16, zero padded past row 1024
__device__ __nv_bfloat16 g_vn_hi[(size_t)BHN * NKP * HD];
__device__ __nv_bfloat16 g_vn_lo[(size_t)BHN * NKP * HD];
__device__ __nv_bfloat16 g_v_hi[(size_t)BHN * NKP * HD];
__device__ __nv_bfloat16 g_v_lo[(size_t)BHN * NKP * HD];

// ---------------- helpers ----------------
__device__ __forceinline__ float2 ffma2(float2 a, float2 b, float2 c) {
    float2 d;
    asm("fma.rn.f32x2 %0, %1, %2, %3;"
        : "=l"(*(unsigned long long*)&d)
        : "l"(*(unsigned long long*)&a),
          "l"(*(unsigned long long*)&b),
          "l"(*(unsigned long long*)&c));
    return d;
}

__device__ __forceinline__ uint32_t smem_u32(const void* p) {
    uint32_t a;
    asm("{ .reg .u64 t; cvta.to.shared.u64 t, %1; cvt.u32.u64 %0, t; }"
        : "=r"(a) : "l"(p));
    return a;
}

__device__ __forceinline__ void ldsm4(uint32_t* r, uint32_t addr) {
    asm volatile("ldmatrix.sync.aligned.m8n8.x4.shared.b16 {%0,%1,%2,%3}, [%4];"
                 : "=r"(r[0]), "=r"(r[1]), "=r"(r[2]), "=r"(r[3]) : "r"(addr));
}
__device__ __forceinline__ void ldsm4t(uint32_t* r, uint32_t addr) {
    asm volatile("ldmatrix.sync.aligned.m8n8.x4.trans.shared.b16 {%0,%1,%2,%3}, [%4];"
                 : "=r"(r[0]), "=r"(r[1]), "=r"(r[2]), "=r"(r[3]) : "r"(addr));
}

__device__ __forceinline__ void mma16816(float* d, const uint32_t* a, const uint32_t* b) {
    asm volatile(
        "mma.sync.aligned.m16n8k16.row.col.f32.bf16.bf16.f32 "
        "{%0,%1,%2,%3}, {%4,%5,%6,%7}, {%8,%9}, {%0,%1,%2,%3};"
        : "+f"(d[0]), "+f"(d[1]), "+f"(d[2]), "+f"(d[3])
        : "r"(a[0]), "r"(a[1]), "r"(a[2]), "r"(a[3]), "r"(b[0]), "r"(b[1]));
}

__device__ __forceinline__ uint32_t pack_bf16x2(float lo, float hi) {
    uint32_t r;
    asm("cvt.rn.bf16x2.f32 %0, %1, %2;" : "=r"(r) : "f"(hi), "f"(lo));
    return r;
}
__device__ __forceinline__ float2 unpack_bf16x2(uint32_t u) {
    __nv_bfloat162 b = *reinterpret_cast<__nv_bfloat162*>(&u);
    return make_float2(__bfloat162float(b.x), __bfloat162float(b.y));
}

// cp.async 16B with zero-fill when !ok
__device__ __forceinline__ void cp16(uint32_t dst, const void* src, bool ok) {
    asm volatile("cp.async.cg.shared.global [%0], [%1], 16, %2;"
                 :: "r"(dst), "l"(src), "r"(ok ? 16u : 0u));
}
#define CP_COMMIT() asm volatile("cp.async.commit_group;" ::: "memory")
#define CP_WAIT1()  asm volatile("cp.async.wait_group 1;" ::: "memory")
#define CP_WAIT0()  asm volatile("cp.async.wait_group 0;" ::: "memory")

// exp(0.125*s - 0.125) for s in [-1,1]: deg-4 Taylor on t in [-0.25, 0]
__device__ __forceinline__ float2 exp_poly2(float2 s) {
    float2 t = ffma2(s, make_float2(0.125f, 0.125f), make_float2(-0.125f, -0.125f));
    float2 hh = ffma2(t, make_float2(1.f/24.f, 1.f/24.f), make_float2(1.f/6.f, 1.f/6.f));
    hh = ffma2(t, hh, make_float2(0.5f, 0.5f));
    hh = ffma2(t, hh, make_float2(1.f, 1.f));
    hh = ffma2(t, hh, make_float2(1.f, 1.f));
    return hh;
}

// ============================================================================
// fp32 -> bf16 hi/lo split
// ============================================================================
__global__ void cvt_kernel(const float* __restrict__ in,
                           __nv_bfloat16* __restrict__ hi,
                           __nv_bfloat16* __restrict__ lo, int n4)
{
    int i = blockIdx.x * blockDim.x + threadIdx.x;
    if (i >= n4) return;
    float4 v = ((const float4*)in)[i];
    float vv[4] = {v.x, v.y, v.z, v.w};
    union { __nv_bfloat16 b[4]; uint2 u; } ph, pl;
#pragma unroll
    for (int j = 0; j < 4; j++) {
        __nv_bfloat16 h = __float2bfloat16(vv[j]);
        ph.b[j] = h;
        pl.b[j] = __float2bfloat16(vv[j] - __bfloat162float(h));
    }
    ((uint2*)hi)[i] = ph.u;
    ((uint2*)lo)[i] = pl.u;
}

// ============================================================================
// mma.sync bf16 hi/lo GEMM: 256 thr, 8 warps, 64x32 warp tiles, cp.async
// double buffer.  Block 128x128, BK=32.  D += Ah*Bh + Ah*Bl + Al*Bh.
// MODE 0 (v):    A row m -> x row (m%SEQ)*B + m/SEQ,  C -> g_v[m][j], N=768
// MODE 1 (proj): A row m -> o_hi/lo row m, C -> out[(m%SEQ)*B + m/SEQ][j]+bias
// ============================================================================
#define STG 5120                    /* 128*SROW elems per buffer */
#define GEMM_SMEM (8 * STG * 2)     /* 2 stages x 4 arrays = 81920 bytes */

template<int MODE, int NOUT>
__global__ __launch_bounds__(256, 2) void mma_gemm(
    const __nv_bfloat16* __restrict__ Ahi, const __nv_bfloat16* __restrict__ Alo,
    const __nv_bfloat16* __restrict__ Bhi, const __nv_bfloat16* __restrict__ Blo,
    const float* __restrict__ bias, float* __restrict__ C)
{
    extern __shared__ __nv_bfloat16 smg[];
    const uint32_t smB = smem_u32(smg);

    const int tid = threadIdx.x;
    const int lane = tid & 31, wid = tid >> 5;
    const int warp_m = wid & 1;        // 0..1 (64 rows)
    const int warp_n = wid >> 1;       // 0..3 (32 cols)
    const int bm = blockIdx.y * 128, bn = blockIdx.x * 128;

    // global loads: 2 threads per row, each covers 16 elems (2x 16B)
    const int lr = tid >> 1, lk = (tid & 1) * 16;
    const int am = bm + lr;
    const bool aok = (am < M_ROWS);
    int arow;
    if (MODE == 0) arow = (am % SEQ) * BATCH + (am / SEQ);
    else           arow = am;
    if (!aok) arow = 0;
    const size_t aoff = (size_t)arow * DIM + lk;
    const size_t boff = (size_t)(bn + lr) * DIM + lk;
    const uint32_t rowb = (uint32_t)(lr * SROW + lk) * 2;

    // ldmatrix frag base offsets
    const int a_r = warp_m * 64 + (lane & 7) + ((lane >> 3) & 1) * 8;
    const int a_k = (lane >> 4) * 8;
    const uint32_t aoffb = (uint32_t)(a_r * SROW + a_k) * 2;
    const int b_n = warp_n * 32 + (lane & 7) + (lane >> 4) * 8;
    const int b_k = ((lane >> 3) & 1) * 8;
    const uint32_t boffb = (uint32_t)(b_n * SROW + b_k) * 2;

    float acc[4][4][4];
#pragma unroll
    for (int i = 0; i < 4; i++)
#pragma unroll
        for (int j = 0; j < 4; j++)
#pragma unroll
            for (int r = 0; r < 4; r++) acc[i][j][r] = 0.f;

#define LOAD_STAGE(ST, GK)                                                    \
    do {                                                                      \
        const uint32_t s0 = smB + (uint32_t)((ST) * 4) * (STG * 2) + rowb;    \
        cp16(s0 + 0 * (STG * 2),      Ahi + aoff + (GK),     aok);            \
        cp16(s0 + 0 * (STG * 2) + 16, Ahi + aoff + (GK) + 8, aok);            \
        cp16(s0 + 1 * (STG * 2),      Alo + aoff + (GK),     aok);            \
        cp16(s0 + 1 * (STG * 2) + 16, Alo + aoff + (GK) + 8, aok);            \
        cp16(s0 + 2 * (STG * 2),      Bhi + boff + (GK),     true);           \
        cp16(s0 + 2 * (STG * 2) + 16, Bhi + boff + (GK) + 8, true);           \
        cp16(s0 + 3 * (STG * 2),      Blo + boff + (GK),     true);           \
        cp16(s0 + 3 * (STG * 2) + 16, Blo + boff + (GK) + 8, true);           \
        CP_COMMIT();                                                          \
    } while (0)

    LOAD_STAGE(0, 0);

#pragma unroll 1
    for (int kc = 0; kc < DIM / 32; kc++) {
        const int st = kc & 1;
        if (kc < DIM / 32 - 1) {
            LOAD_STAGE(st ^ 1, (size_t)(kc + 1) * 32);
            CP_WAIT1();
        } else {
            CP_WAIT0();
        }
        __syncthreads();

        const uint32_t aAh = smB + (uint32_t)(st * 4 + 0) * (STG * 2) + aoffb;
        const uint32_t aAl = smB + (uint32_t)(st * 4 + 1) * (STG * 2) + aoffb;
        const uint32_t aBh = smB + (uint32_t)(st * 4 + 2) * (STG * 2) + boffb;
        const uint32_t aBl = smB + (uint32_t)(st * 4 + 3) * (STG * 2) + boffb;

#pragma unroll
        for (int kh = 0; kh < 2; kh++) {
            const uint32_t kb = kh * 32;
            uint32_t ah[4][4], al[4][4];
#pragma unroll
            for (int mi = 0; mi < 4; mi++) {
                ldsm4(ah[mi], aAh + mi * (16 * SROW * 2) + kb);
                ldsm4(al[mi], aAl + mi * (16 * SROW * 2) + kb);
            }
#pragma unroll
            for (int np = 0; np < 2; np++) {
                uint32_t bh2[4], bl2[4];
                ldsm4(bh2, aBh + np * (16 * SROW * 2) + kb);
                ldsm4(bl2, aBl + np * (16 * SROW * 2) + kb);
#pragma unroll
                for (int mi = 0; mi < 4; mi++) {
                    mma16816(acc[mi][2 * np],     ah[mi], bh2);
                    mma16816(acc[mi][2 * np],     ah[mi], bl2);
                    mma16816(acc[mi][2 * np],     al[mi], bh2);
                    mma16816(acc[mi][2 * np + 1], ah[mi], bh2 + 2);
                    mma16816(acc[mi][2 * np + 1], ah[mi], bl2 + 2);
                    mma16816(acc[mi][2 * np + 1], al[mi], bh2 + 2);
                }
            }
        }
        __syncthreads();
    }

    // epilogue
    const int col0 = bn + warp_n * 32 + (lane & 3) * 2;
    const int row0 = bm + warp_m * 64 + (lane >> 2);
#pragma unroll
    for (int mi = 0; mi < 4; mi++) {
#pragma unroll
        for (int half = 0; half < 2; half++) {
            const int m = row0 + mi * 16 + half * 8;
            if (m >= M_ROWS) continue;
            size_t crow;
            if (MODE == 0) crow = (size_t)m * NOUT;
            else           crow = (size_t)((m % SEQ) * BATCH + (m / SEQ)) * NOUT;
#pragma unroll
            for (int nj = 0; nj < 4; nj++) {
                const int col = col0 + nj * 8;
                float2 o = make_float2(acc[mi][nj][2 * half], acc[mi][nj][2 * half + 1]);
                if (MODE == 1) {
                    float2 bv = *(const float2*)&bias[col];
                    o.x += bv.x; o.y += bv.y;
                }
                *(float2*)&C[crow + col] = o;
            }
        }
    }
}

// ============================================================================
// prep (norm fused): per (bh,row) compute inv-norm, write bf16 hi/lo of
// vn = v*inv and of raw v; zero-pad rows >= SEQ. v at g_v[m][h*64].
// ============================================================================
__global__ void prep_kernel(const float* __restrict__ v,
                            __nv_bfloat16* __restrict__ vnh, __nv_bfloat16* __restrict__ vnl,
                            __nv_bfloat16* __restrict__ vh_, __nv_bfloat16* __restrict__ vl_)
{
    int idx = blockIdx.x * blockDim.x + threadIdx.x;
    if (idx >= BHN * NKP) return;
    const int bh = idx / NKP, row = idx % NKP;
    const int b = bh / NH, h = bh % NH;
    const size_t dst = (size_t)idx * HD;
    if (row < SEQ) {
        const float* src = v + (size_t)(b * SEQ + row) * DIM + h * HD;
        float4 vbuf[16];
        float acc = 0.f;
#pragma unroll
        for (int c = 0; c < 16; c++) {
            float4 t = *(const float4*)(src + 4 * c);
            vbuf[c] = t;
            acc += t.x * t.x + t.y * t.y + t.z * t.z + t.w * t.w;
        }
        const float iv = 1.f / fmaxf(sqrtf(acc), 1e-6f);
#pragma unroll 4
        for (int c = 0; c < 16; c++) {
            float vv[4] = {vbuf[c].x, vbuf[c].y, vbuf[c].z, vbuf[c].w};
            union { __nv_bfloat16 b[4]; uint2 u; } nh, nl, rh, rl;
#pragma unroll
            for (int j = 0; j < 4; j++) {
                float vn = vv[j] * iv;
                __nv_bfloat16 h1 = __float2bfloat16(vn);
                nh.b[j] = h1;
                nl.b[j] = __float2bfloat16(vn - __bfloat162float(h1));
                __nv_bfloat16 h2 = __float2bfloat16(vv[j]);
                rh.b[j] = h2;
                rl.b[j] = __float2bfloat16(vv[j] - __bfloat162float(h2));
            }
            *(uint2*)(vnh + dst + 4 * c) = nh.u;
            *(uint2*)(vnl + dst + 4 * c) = nl.u;
            *(uint2*)(vh_ + dst + 4 * c) = rh.u;
            *(uint2*)(vl_ + dst + 4 * c) = rl.u;
        }
    } else {
        uint2 z = {0, 0};
#pragma unroll 4
        for (int c = 0; c < HD; c += 4) {
            *(uint2*)(vnh + dst + c) = z;
            *(uint2*)(vnl + dst + c) = z;
            *(uint2*)(vh_ + dst + c) = z;
            *(uint2*)(vl_ + dst + c) = z;
        }
    }
}

// ============================================================================
// Row-0 attention, k-free: q0 = Wq x0 (exact fp32), u = Wk^T q0, scores
// s_j = u . x_j  (the K matrix is never materialized). PV from g_v.
// ============================================================================
__global__ __launch_bounds__(256) void row0_kernel(const float* __restrict__ x,
                                                   const float* __restrict__ w_qkv,
                                                   const float* __restrict__ v,
                                                   __nv_bfloat16* __restrict__ ohi,
                                                   __nv_bfloat16* __restrict__ olo)
{
    __shared__ float q0s[HD];
    __shared__ float us[DIM];
    __shared__ float sc[SEQ];
    __shared__ float red[256];
    __shared__ float part[4][HD];
    const int tid = threadIdx.x;
    const int b = blockIdx.x / NH, h = blockIdx.x % NH;
    const int d = tid & 63, pi = tid >> 6;

    // ---- q0[d] = 0.125 * sum_k x[0,b,k] * Wq[h*64+d][k]   (exact fp32)
    {
        const float* xr = x + (size_t)b * DIM;          // n=0 row
        const float* wrow = w_qkv + (size_t)(h * HD + d) * DIM;
        float acc = 0.f;
        const int k0 = pi * 192;
#pragma unroll 4
        for (int k = k0; k < k0 + 192; k += 4) {
            float4 xv = *(const float4*)(xr + k);
            float4 wv = *(const float4*)(wrow + k);
            acc += xv.x * wv.x + xv.y * wv.y + xv.z * wv.z + xv.w * wv.w;
        }
        part[pi][d] = acc;
        __syncthreads();
        if (tid < HD)
            q0s[tid] = 0.125f * (part[0][tid] + part[1][tid] + part[2][tid] + part[3][tid]);
        __syncthreads();
    }

    // ---- u[k] = sum_d q0s[d] * Wk[h*64+d][k]  (Wk = w_qkv rows 768..1535)
    {
        const float* wk = w_qkv + ((size_t)DIM + h * HD) * DIM;
        for (int k = tid; k < DIM; k += 256) {
            float acc = 0.f;
#pragma unroll 8
            for (int dd = 0; dd < HD; dd++)
                acc += q0s[dd] * wk[(size_t)dd * DIM + k];
            us[k] = acc;
        }
    }
    __syncthreads();

    // ---- scores: s_j = u . x[j,b,:]
    float lmax = -1e30f;
    for (int j = tid; j < SEQ; j += 256) {
        const float4* xr = (const float4*)(x + (size_t)(j * BATCH + b) * DIM);
        float acc = 0.f;
#pragma unroll 8
        for (int c = 0; c < DIM / 4; c++) {
            float4 t = xr[c];
            acc += us[4*c] * t.x + us[4*c+1] * t.y + us[4*c+2] * t.z + us[4*c+3] * t.w;
        }
        sc[j] = acc;
        lmax = fmaxf(lmax, acc);
    }
    red[tid] = lmax; __syncthreads();
    for (int s = 128; s > 0; s >>= 1) {
        if (tid < s) red[tid] = fmaxf(red[tid], red[tid + s]);
        __syncthreads();
    }
    float mval = red[0];
    __syncthreads();

    float lsum = 0.f;
    for (int j = tid; j < SEQ; j += 256) {
        float p = __expf(sc[j] - mval);
        sc[j] = p;
        lsum += p;
    }
    red[tid] = lsum; __syncthreads();
    for (int s = 128; s > 0; s >>= 1) {
        if (tid < s) red[tid] += red[tid + s];
        __syncthreads();
    }
    float l = red[0];
    __syncthreads();

    float acc = 0.f;
    const float* vbase = v + (size_t)(b * SEQ) * DIM + h * HD;
    for (int j = pi; j < SEQ; j += 4)
        acc += sc[j] * vbase[(size_t)j * DIM + d];
    part[pi][d] = acc;
    __syncthreads();
    if (tid < HD) {
        float s = (part[0][tid] + part[1][tid] + part[2][tid] + part[3][tid]) / l;
        const size_t o = (size_t)(b * SEQ) * DIM + h * HD + tid;
        __nv_bfloat16 hh = __float2bfloat16(s);
        ohi[o] = hh;
        olo[o] = __float2bfloat16(s - __bfloat162float(hh));
    }
}

// ============================================================================
// Fused FA2-style VV attention, rows 1..1024.
// S = (Qh+Ql)·Kh (2-pass); PV = Ph·Vh + Ph·Vl + Pl·Vh (3-pass).
// Writes bf16 hi/lo output directly.
// ============================================================================
__global__ __launch_bounds__(256, 1)
void vv_mma_kernel(const __nv_bfloat16* __restrict__ vnh, const __nv_bfloat16* __restrict__ vnl,
                   const __nv_bfloat16* __restrict__ vvh, const __nv_bfloat16* __restrict__ vvl,
                   __nv_bfloat16* __restrict__ ohi, __nv_bfloat16* __restrict__ olo)
{
    extern __shared__ __nv_bfloat16 sm[];
    __nv_bfloat16* sKh = sm;
    __nv_bfloat16* sVh = sm + 128 * SROW2;
    __nv_bfloat16* sVl = sm + 2 * 128 * SROW2;

    const int tid = threadIdx.x, lane = tid & 31, wid = tid >> 5;
    const int bh = blockIdx.y, qt = blockIdx.x;
    const int b = bh / NH, h = bh % NH;
    const int q0 = 1 + qt * 128;
    const size_t base = (size_t)bh * NKP * HD;

    const int ld_r = tid >> 1, ld_c = (tid & 1) * 32;

    // stage Q (hi -> sKh, lo -> sVh), extract fragments
    {
        const size_t g = base + (size_t)(q0 + ld_r) * HD + ld_c;
        uint4* dh = (uint4*)(sKh + ld_r * SROW2 + ld_c);
        uint4* dl = (uint4*)(sVh + ld_r * SROW2 + ld_c);
        const uint4* p1 = (const uint4*)(vnh + g);
        const uint4* p2 = (const uint4*)(vnl + g);
#pragma unroll
        for (int i = 0; i < 4; i++) { dh[i] = p1[i]; dl[i] = p2[i]; }
    }
    __syncthreads();
    uint32_t qh[4][4], ql[4][4];
    {
        const int a_r = wid * 16 + (lane & 7) + ((lane >> 3) & 1) * 8;
        const int a_k = (lane >> 4) * 8;
        const uint32_t ah = smem_u32(sKh) + (uint32_t)(a_r * SROW2 + a_k) * 2;
        const uint32_t al = smem_u32(sVh) + (uint32_t)(a_r * SROW2 + a_k) * 2;
#pragma unroll
        for (int kt = 0; kt < 4; kt++) {
            ldsm4(qh[kt], ah + kt * 16 * 2);
            ldsm4(ql[kt], al + kt * 16 * 2);
        }
    }
    __syncthreads();

    float oacc[8][4];
#pragma unroll
    for (int g = 0; g < 8; g++)
#pragma unroll
        for (int r = 0; r < 4; r++) oacc[g][r] = 0.f;
    float la = 0.f, lb = 0.f;

    const int b_n = (lane & 7) + (lane >> 4) * 8;
    const int b_k = ((lane >> 3) & 1) * 8;
    const int t_r = lane & 15, t_c = (lane >> 4) * 8;
    const uint32_t sKh_u = smem_u32(sKh);
    const uint32_t sVh_u = smem_u32(sVh);
    const uint32_t sVl_u = smem_u32(sVl);

#pragma unroll 1
    for (int ktile = 0; ktile < 9; ktile++) {
        {
            const size_t g = base + (size_t)(ktile * 128 + ld_r) * HD + ld_c;
            uint4* d1 = (uint4*)(sKh + ld_r * SROW2 + ld_c);
            uint4* d3 = (uint4*)(sVh + ld_r * SROW2 + ld_c);
            uint4* d4 = (uint4*)(sVl + ld_r * SROW2 + ld_c);
            const uint4* p1 = (const uint4*)(vnh + g);
            const uint4* p3 = (const uint4*)(vvh + g);
            const uint4* p4 = (const uint4*)(vvl + g);
#pragma unroll
            for (int i = 0; i < 4; i++) { d1[i] = p1[i]; d3[i] = p3[i]; d4[i] = p4[i]; }
        }
        __syncthreads();

        // scores: 2-pass (Qh + Ql) x Kh
        float p[16][4];
#pragma unroll
        for (int f = 0; f < 16; f++)
#pragma unroll
            for (int r = 0; r < 4; r++) p[f][r] = 0.f;

#pragma unroll
        for (int kt = 0; kt < 4; kt++) {
#pragma unroll
            for (int g = 0; g < 8; g++) {
                uint32_t kh_[4];
                const uint32_t off = (uint32_t)((g * 16 + b_n) * SROW2 + kt * 16 + b_k) * 2;
                ldsm4(kh_, sKh_u + off);
                mma16816(p[2*g],   qh[kt], kh_);
                mma16816(p[2*g],   ql[kt], kh_);
                mma16816(p[2*g+1], qh[kt], kh_ + 2);
                mma16816(p[2*g+1], ql[kt], kh_ + 2);
            }
        }

        // softmax probs (fixed max), accumulate l
#pragma unroll
        for (int f = 0; f < 16; f++) {
            float2 e0 = exp_poly2(make_float2(p[f][0], p[f][1]));
            float2 e1 = exp_poly2(make_float2(p[f][2], p[f][3]));
            p[f][0] = e0.x; p[f][1] = e0.y; p[f][2] = e1.x; p[f][3] = e1.y;
            la += e0.x + e0.y;
            lb += e1.x + e1.y;
        }

        // PV: 3-pass Ph·Vh + Ph·Vl + Pl·Vh
#pragma unroll
        for (int kt = 0; kt < 8; kt++) {
            uint32_t pah[4], pal[4];
            {
                const float* sA = p[2 * kt];
                const float* sB = p[2 * kt + 1];
                pah[0] = pack_bf16x2(sA[0], sA[1]);
                pah[1] = pack_bf16x2(sA[2], sA[3]);
                pah[2] = pack_bf16x2(sB[0], sB[1]);
                pah[3] = pack_bf16x2(sB[2], sB[3]);
#pragma unroll
                for (int r4 = 0; r4 < 4; r4++) {
                    float2 fh = unpack_bf16x2(pah[r4]);
                    const float* s = (r4 < 2) ? sA : sB;
                    const int o = (r4 & 1) * 2;
                    pal[r4] = pack_bf16x2(s[o] - fh.x, s[o + 1] - fh.y);
                }
            }
#pragma unroll
            for (int g = 0; g < 4; g++) {
                uint32_t vh_[4], vl_[4];
                const uint32_t off = (uint32_t)((kt * 16 + t_r) * SROW2 + g * 16 + t_c) * 2;
                ldsm4t(vh_, sVh_u + off);
                ldsm4t(vl_, sVl_u + off);
                mma16816(oacc[2*g],   pah, vh_);
                mma16816(oacc[2*g],   pah, vl_);
                mma16816(oacc[2*g],   pal, vh_);
                mma16816(oacc[2*g+1], pah, vh_ + 2);
                mma16816(oacc[2*g+1], pah, vl_ + 2);
                mma16816(oacc[2*g+1], pal, vh_ + 2);
            }
        }
        __syncthreads();
    }

    // l reduce + pad correction + hi/lo output
    la += __shfl_xor_sync(0xffffffffu, la, 1);
    la += __shfl_xor_sync(0xffffffffu, la, 2);
    lb += __shfl_xor_sync(0xffffffffu, lb, 1);
    lb += __shfl_xor_sync(0xffffffffu, lb, 2);
    float P0;
    {
        float t = -0.125f;
        float hh = fmaf(t, 1.f/24.f, 1.f/6.f);
        hh = fmaf(t, hh, 0.5f);
        hh = fmaf(t, hh, 1.f);
        hh = fmaf(t, hh, 1.f);
        P0 = hh;
    }
    la -= 127.f * P0;
    lb -= 127.f * P0;
    const float ia = 1.f / la, ib = 1.f / lb;

    const int row_a = q0 + wid * 16 + (lane >> 2);
    const int col0 = h * HD + (lane & 3) * 2;
    const size_t oa = (size_t)(b * SEQ + row_a) * DIM;
    const size_t ob = (size_t)(b * SEQ + row_a + 8) * DIM;
#pragma unroll
    for (int g = 0; g < 8; g++) {
        float x0 = oacc[g][0] * ia, x1 = oacc[g][1] * ia;
        float y0 = oacc[g][2] * ib, y1 = oacc[g][3] * ib;
        uint32_t xh = pack_bf16x2(x0, x1);
        uint32_t yh = pack_bf16x2(y0, y1);
        float2 fxh = unpack_bf16x2(xh);
        float2 fyh = unpack_bf16x2(yh);
        uint32_t xl = pack_bf16x2(x0 - fxh.x, x1 - fxh.y);
        uint32_t yl = pack_bf16x2(y0 - fyh.x, y1 - fyh.y);
        *(uint32_t*)(ohi + oa + col0 + g * 8) = xh;
        *(uint32_t*)(olo + oa + col0 + g * 8) = xl;
        *(uint32_t*)(ohi + ob + col0 + g * 8) = yh;
        *(uint32_t*)(olo + ob + col0 + g * 8) = yl;
    }
}

// ============================================================================
extern "C" void kernel_launch(void* const* d_in, const int* in_sizes, int n_in,
                              void* d_out, int out_size)
{
    const float* x      = (const float*)d_in[0];
    const float* w_qkv  = (const float*)d_in[1];
    const float* w_proj = (const float*)d_in[2];
    const float* b_proj = (const float*)d_in[3];
    float* out = (float*)d_out;

    float *p_v;
    cudaGetSymbolAddress((void**)&p_v, g_v);
    __nv_bfloat16 *p_xh, *p_xl, *p_wvh, *p_wvl, *p_oh, *p_ol, *p_wph, *p_wpl;
    __nv_bfloat16 *p_vnh, *p_vnl, *p_vhh, *p_vll;
    cudaGetSymbolAddress((void**)&p_xh,  g_x_hi);
    cudaGetSymbolAddress((void**)&p_xl,  g_x_lo);
    cudaGetSymbolAddress((void**)&p_wvh, g_wv_hi);
    cudaGetSymbolAddress((void**)&p_wvl, g_wv_lo);
    cudaGetSymbolAddress((void**)&p_oh,  g_o_hi);
    cudaGetSymbolAddress((void**)&p_ol,  g_o_lo);
    cudaGetSymbolAddress((void**)&p_wph, g_wp_hi);
    cudaGetSymbolAddress((void**)&p_wpl, g_wp_lo);
    cudaGetSymbolAddress((void**)&p_vnh, g_vn_hi);
    cudaGetSymbolAddress((void**)&p_vnl, g_vn_lo);
    cudaGetSymbolAddress((void**)&p_vhh, g_v_hi);
    cudaGetSymbolAddress((void**)&p_vll, g_v_lo);

    const int vv_smem = 3 * 128 * SROW2 * 2;   // 55296 bytes
    cudaFuncSetAttribute(vv_mma_kernel, cudaFuncAttributeMaxDynamicSharedMemorySize, vv_smem);
    cudaFuncSetAttribute(mma_gemm<0, DIM>, cudaFuncAttributeMaxDynamicSharedMemorySize, GEMM_SMEM);
    cudaFuncSetAttribute(mma_gemm<1, DIM>, cudaFuncAttributeMaxDynamicSharedMemorySize, GEMM_SMEM);

    // 0) bf16 hi/lo conversions: x, w_qkv rows 1536..2304 (v weights), w_proj
    {
        int n4x = M_ROWS * DIM / 4;
        cvt_kernel<<<(n4x + 255) / 256, 256>>>(x, p_xh, p_xl, n4x);
        int n4w = DIM * DIM / 4;
        cvt_kernel<<<(n4w + 255) / 256, 256>>>(w_qkv + (size_t)2 * DIM * DIM, p_wvh, p_wvl, n4w);
        cvt_kernel<<<(n4w + 255) / 256, 256>>>(w_proj, p_wph, p_wpl, n4w);
    }
    // 1) V GEMM (v only; k eliminated via u = Wk^T q0 trick) -> g_v
    {
        dim3 grid(DIM / 128, (M_ROWS + 127) / 128);
        mma_gemm<0, DIM><<<grid, 256, GEMM_SMEM>>>(p_xh, p_xl, p_wvh, p_wvl, nullptr, p_v);
    }
    // 2) prep (norm fused): vn/v bf16 hi/lo padded operands
    {
        int total = BHN * NKP;
        prep_kernel<<<(total + 255) / 256, 256>>>(p_v, p_vnh, p_vnl, p_vhh, p_vll);
    }
    // 3) row-0 QK attention (k-free: s_j = (Wk^T q0) . x_j, exact fp32)
    row0_kernel<<<BHN, 256>>>(x, w_qkv, p_v, p_oh, p_ol);
    // 4) VV cosine attention rows 1..1024
    {
        dim3 grid(8, BHN);
        vv_mma_kernel<<<grid, 256, vv_smem>>>(p_vnh, p_vnl, p_vhh, p_vll, p_oh, p_ol);
    }
    // 5) proj GEMM + bias -> out
    {
        dim3 grid(DIM / 128, (M_ROWS + 127) / 128);
        mma_gemm<1, DIM><<<grid, 256, GEMM_SMEM>>>(p_oh, p_ol, p_wph, p_wpl, b_proj, out);
    }
}

// round 13
// speedup vs baseline: 1.0293x; 1.0293x over previous
#include <cuda_runtime.h>
#include <cuda_bf16.h>
#include <cstdint>

#define NH    12
#define HD    64
#define SEQ   1025
#define BATCH 8
#define DIM   768
#define M_ROWS (BATCH * SEQ)   /* 8200 */
#define BHN   (BATCH * NH)     /* 96 */
#define NKP   1152             /* keys padded to 9*128 */
#define SROW2 72               /* padded smem row (bf16) for 64-dim tiles */
#define SROW  40               /* padded smem row (bf16) for 32-wide k-chunks */

// ---------------- scratch (device globals: allocation-free) ----------------
__device__ float g_v[(size_t)M_ROWS * DIM];    // v only (k eliminated algebraically)

__device__ __nv_bfloat16 g_x_hi[(size_t)M_ROWS * DIM];
__device__ __nv_bfloat16 g_x_lo[(size_t)M_ROWS * DIM];
__device__ __nv_bfloat16 g_wv_hi[(size_t)DIM * DIM];
__device__ __nv_bfloat16 g_wv_lo[(size_t)DIM * DIM];
__device__ __nv_bfloat16 g_o_hi[(size_t)M_ROWS * DIM];
__device__ __nv_bfloat16 g_o_lo[(size_t)M_ROWS * DIM];
__device__ __nv_bfloat16 g_wp_hi[(size_t)DIM * DIM];
__device__ __nv_bfloat16 g_wp_lo[(size_t)DIM * DIM];

// VV attention operands: [bh][1152][64] bf16, zero padded past row 1024
__device__ __nv_bfloat16 g_vn_hi[(size_t)BHN * NKP * HD];
__device__ __nv_bfloat16 g_vn_lo[(size_t)BHN * NKP * HD];
__device__ __nv_bfloat16 g_v_hi[(size_t)BHN * NKP * HD];
__device__ __nv_bfloat16 g_v_lo[(size_t)BHN * NKP * HD];

// ---------------- helpers ----------------
__device__ __forceinline__ float2 ffma2(float2 a, float2 b, float2 c) {
    float2 d;
    asm("fma.rn.f32x2 %0, %1, %2, %3;"
        : "=l"(*(unsigned long long*)&d)
        : "l"(*(unsigned long long*)&a),
          "l"(*(unsigned long long*)&b),
          "l"(*(unsigned long long*)&c));
    return d;
}

__device__ __forceinline__ uint32_t smem_u32(const void* p) {
    uint32_t a;
    asm("{ .reg .u64 t; cvta.to.shared.u64 t, %1; cvt.u32.u64 %0, t; }"
        : "=r"(a) : "l"(p));
    return a;
}

__device__ __forceinline__ void ldsm4(uint32_t* r, uint32_t addr) {
    asm volatile("ldmatrix.sync.aligned.m8n8.x4.shared.b16 {%0,%1,%2,%3}, [%4];"
                 : "=r"(r[0]), "=r"(r[1]), "=r"(r[2]), "=r"(r[3]) : "r"(addr));
}
__device__ __forceinline__ void ldsm4t(uint32_t* r, uint32_t addr) {
    asm volatile("ldmatrix.sync.aligned.m8n8.x4.trans.shared.b16 {%0,%1,%2,%3}, [%4];"
                 : "=r"(r[0]), "=r"(r[1]), "=r"(r[2]), "=r"(r[3]) : "r"(addr));
}

__device__ __forceinline__ void mma16816(float* d, const uint32_t* a, const uint32_t* b) {
    asm volatile(
        "mma.sync.aligned.m16n8k16.row.col.f32.bf16.bf16.f32 "
        "{%0,%1,%2,%3}, {%4,%5,%6,%7}, {%8,%9}, {%0,%1,%2,%3};"
        : "+f"(d[0]), "+f"(d[1]), "+f"(d[2]), "+f"(d[3])
        : "r"(a[0]), "r"(a[1]), "r"(a[2]), "r"(a[3]), "r"(b[0]), "r"(b[1]));
}

__device__ __forceinline__ uint32_t pack_bf16x2(float lo, float hi) {
    uint32_t r;
    asm("cvt.rn.bf16x2.f32 %0, %1, %2;" : "=r"(r) : "f"(hi), "f"(lo));
    return r;
}
__device__ __forceinline__ float2 unpack_bf16x2(uint32_t u) {
    __nv_bfloat162 b = *reinterpret_cast<__nv_bfloat162*>(&u);
    return make_float2(__bfloat162float(b.x), __bfloat162float(b.y));
}

// cp.async 16B with zero-fill when !ok
__device__ __forceinline__ void cp16(uint32_t dst, const void* src, bool ok) {
    asm volatile("cp.async.cg.shared.global [%0], [%1], 16, %2;"
                 :: "r"(dst), "l"(src), "r"(ok ? 16u : 0u));
}
#define CP_COMMIT() asm volatile("cp.async.commit_group;" ::: "memory")
#define CP_WAIT1()  asm volatile("cp.async.wait_group 1;" ::: "memory")
#define CP_WAIT0()  asm volatile("cp.async.wait_group 0;" ::: "memory")

// exp(0.125*s - 0.125) for s in [-1,1]: deg-4 Taylor on t in [-0.25, 0]
__device__ __forceinline__ float2 exp_poly2(float2 s) {
    float2 t = ffma2(s, make_float2(0.125f, 0.125f), make_float2(-0.125f, -0.125f));
    float2 hh = ffma2(t, make_float2(1.f/24.f, 1.f/24.f), make_float2(1.f/6.f, 1.f/6.f));
    hh = ffma2(t, hh, make_float2(0.5f, 0.5f));
    hh = ffma2(t, hh, make_float2(1.f, 1.f));
    hh = ffma2(t, hh, make_float2(1.f, 1.f));
    return hh;
}

__device__ __forceinline__ float warp_sum(float v) {
    v += __shfl_xor_sync(0xffffffffu, v, 16);
    v += __shfl_xor_sync(0xffffffffu, v, 8);
    v += __shfl_xor_sync(0xffffffffu, v, 4);
    v += __shfl_xor_sync(0xffffffffu, v, 2);
    v += __shfl_xor_sync(0xffffffffu, v, 1);
    return v;
}

// ============================================================================
// fp32 -> bf16 hi/lo split
// ============================================================================
__global__ void cvt_kernel(const float* __restrict__ in,
                           __nv_bfloat16* __restrict__ hi,
                           __nv_bfloat16* __restrict__ lo, int n4)
{
    int i = blockIdx.x * blockDim.x + threadIdx.x;
    if (i >= n4) return;
    float4 v = ((const float4*)in)[i];
    float vv[4] = {v.x, v.y, v.z, v.w};
    union { __nv_bfloat16 b[4]; uint2 u; } ph, pl;
#pragma unroll
    for (int j = 0; j < 4; j++) {
        __nv_bfloat16 h = __float2bfloat16(vv[j]);
        ph.b[j] = h;
        pl.b[j] = __float2bfloat16(vv[j] - __bfloat162float(h));
    }
    ((uint2*)hi)[i] = ph.u;
    ((uint2*)lo)[i] = pl.u;
}

// ============================================================================
// mma.sync bf16 hi/lo GEMM: 256 thr, 8 warps, 64x32 warp tiles, cp.async
// double buffer.  Block 128x128, BK=32.  D += Ah*Bh + Ah*Bl + Al*Bh.
// MODE 0 (v):    A row m -> x row (m%SEQ)*B + m/SEQ,  C -> g_v[m][j], N=768
// MODE 1 (proj): A row m -> o_hi/lo row m, C -> out[(m%SEQ)*B + m/SEQ][j]+bias
// ============================================================================
#define STG 5120                    /* 128*SROW elems per buffer */
#define GEMM_SMEM (8 * STG * 2)     /* 2 stages x 4 arrays = 81920 bytes */

template<int MODE, int NOUT>
__global__ __launch_bounds__(256, 2) void mma_gemm(
    const __nv_bfloat16* __restrict__ Ahi, const __nv_bfloat16* __restrict__ Alo,
    const __nv_bfloat16* __restrict__ Bhi, const __nv_bfloat16* __restrict__ Blo,
    const float* __restrict__ bias, float* __restrict__ C)
{
    extern __shared__ __nv_bfloat16 smg[];
    const uint32_t smB = smem_u32(smg);

    const int tid = threadIdx.x;
    const int lane = tid & 31, wid = tid >> 5;
    const int warp_m = wid & 1;        // 0..1 (64 rows)
    const int warp_n = wid >> 1;       // 0..3 (32 cols)
    const int bm = blockIdx.y * 128, bn = blockIdx.x * 128;

    const int lr = tid >> 1, lk = (tid & 1) * 16;
    const int am = bm + lr;
    const bool aok = (am < M_ROWS);
    int arow;
    if (MODE == 0) arow = (am % SEQ) * BATCH + (am / SEQ);
    else           arow = am;
    if (!aok) arow = 0;
    const size_t aoff = (size_t)arow * DIM + lk;
    const size_t boff = (size_t)(bn + lr) * DIM + lk;
    const uint32_t rowb = (uint32_t)(lr * SROW + lk) * 2;

    const int a_r = warp_m * 64 + (lane & 7) + ((lane >> 3) & 1) * 8;
    const int a_k = (lane >> 4) * 8;
    const uint32_t aoffb = (uint32_t)(a_r * SROW + a_k) * 2;
    const int b_n = warp_n * 32 + (lane & 7) + (lane >> 4) * 8;
    const int b_k = ((lane >> 3) & 1) * 8;
    const uint32_t boffb = (uint32_t)(b_n * SROW + b_k) * 2;

    float acc[4][4][4];
#pragma unroll
    for (int i = 0; i < 4; i++)
#pragma unroll
        for (int j = 0; j < 4; j++)
#pragma unroll
            for (int r = 0; r < 4; r++) acc[i][j][r] = 0.f;

#define LOAD_STAGE(ST, GK)                                                    \
    do {                                                                      \
        const uint32_t s0 = smB + (uint32_t)((ST) * 4) * (STG * 2) + rowb;    \
        cp16(s0 + 0 * (STG * 2),      Ahi + aoff + (GK),     aok);            \
        cp16(s0 + 0 * (STG * 2) + 16, Ahi + aoff + (GK) + 8, aok);            \
        cp16(s0 + 1 * (STG * 2),      Alo + aoff + (GK),     aok);            \
        cp16(s0 + 1 * (STG * 2) + 16, Alo + aoff + (GK) + 8, aok);            \
        cp16(s0 + 2 * (STG * 2),      Bhi + boff + (GK),     true);           \
        cp16(s0 + 2 * (STG * 2) + 16, Bhi + boff + (GK) + 8, true);           \
        cp16(s0 + 3 * (STG * 2),      Blo + boff + (GK),     true);           \
        cp16(s0 + 3 * (STG * 2) + 16, Blo + boff + (GK) + 8, true);           \
        CP_COMMIT();                                                          \
    } while (0)

    LOAD_STAGE(0, 0);

#pragma unroll 1
    for (int kc = 0; kc < DIM / 32; kc++) {
        const int st = kc & 1;
        if (kc < DIM / 32 - 1) {
            LOAD_STAGE(st ^ 1, (size_t)(kc + 1) * 32);
            CP_WAIT1();
        } else {
            CP_WAIT0();
        }
        __syncthreads();

        const uint32_t aAh = smB + (uint32_t)(st * 4 + 0) * (STG * 2) + aoffb;
        const uint32_t aAl = smB + (uint32_t)(st * 4 + 1) * (STG * 2) + aoffb;
        const uint32_t aBh = smB + (uint32_t)(st * 4 + 2) * (STG * 2) + boffb;
        const uint32_t aBl = smB + (uint32_t)(st * 4 + 3) * (STG * 2) + boffb;

#pragma unroll
        for (int kh = 0; kh < 2; kh++) {
            const uint32_t kb = kh * 32;
            uint32_t ah[4][4], al[4][4];
#pragma unroll
            for (int mi = 0; mi < 4; mi++) {
                ldsm4(ah[mi], aAh + mi * (16 * SROW * 2) + kb);
                ldsm4(al[mi], aAl + mi * (16 * SROW * 2) + kb);
            }
#pragma unroll
            for (int np = 0; np < 2; np++) {
                uint32_t bh2[4], bl2[4];
                ldsm4(bh2, aBh + np * (16 * SROW * 2) + kb);
                ldsm4(bl2, aBl + np * (16 * SROW * 2) + kb);
#pragma unroll
                for (int mi = 0; mi < 4; mi++) {
                    mma16816(acc[mi][2 * np],     ah[mi], bh2);
                    mma16816(acc[mi][2 * np],     ah[mi], bl2);
                    mma16816(acc[mi][2 * np],     al[mi], bh2);
                    mma16816(acc[mi][2 * np + 1], ah[mi], bh2 + 2);
                    mma16816(acc[mi][2 * np + 1], ah[mi], bl2 + 2);
                    mma16816(acc[mi][2 * np + 1], al[mi], bh2 + 2);
                }
            }
        }
        __syncthreads();
    }

    const int col0 = bn + warp_n * 32 + (lane & 3) * 2;
    const int row0 = bm + warp_m * 64 + (lane >> 2);
#pragma unroll
    for (int mi = 0; mi < 4; mi++) {
#pragma unroll
        for (int half = 0; half < 2; half++) {
            const int m = row0 + mi * 16 + half * 8;
            if (m >= M_ROWS) continue;
            size_t crow;
            if (MODE == 0) crow = (size_t)m * NOUT;
            else           crow = (size_t)((m % SEQ) * BATCH + (m / SEQ)) * NOUT;
#pragma unroll
            for (int nj = 0; nj < 4; nj++) {
                const int col = col0 + nj * 8;
                float2 o = make_float2(acc[mi][nj][2 * half], acc[mi][nj][2 * half + 1]);
                if (MODE == 1) {
                    float2 bv = *(const float2*)&bias[col];
                    o.x += bv.x; o.y += bv.y;
                }
                *(float2*)&C[crow + col] = o;
            }
        }
    }
}

// ============================================================================
// prep (norm fused): per (bh,row) compute inv-norm, write bf16 hi/lo of
// vn = v*inv and of raw v; zero-pad rows >= SEQ. v at g_v[m][h*64].
// ============================================================================
__global__ void prep_kernel(const float* __restrict__ v,
                            __nv_bfloat16* __restrict__ vnh, __nv_bfloat16* __restrict__ vnl,
                            __nv_bfloat16* __restrict__ vh_, __nv_bfloat16* __restrict__ vl_)
{
    int idx = blockIdx.x * blockDim.x + threadIdx.x;
    if (idx >= BHN * NKP) return;
    const int bh = idx / NKP, row = idx % NKP;
    const int b = bh / NH, h = bh % NH;
    const size_t dst = (size_t)idx * HD;
    if (row < SEQ) {
        const float* src = v + (size_t)(b * SEQ + row) * DIM + h * HD;
        float4 vbuf[16];
        float acc = 0.f;
#pragma unroll
        for (int c = 0; c < 16; c++) {
            float4 t = *(const float4*)(src + 4 * c);
            vbuf[c] = t;
            acc += t.x * t.x + t.y * t.y + t.z * t.z + t.w * t.w;
        }
        const float iv = 1.f / fmaxf(sqrtf(acc), 1e-6f);
#pragma unroll 4
        for (int c = 0; c < 16; c++) {
            float vv[4] = {vbuf[c].x, vbuf[c].y, vbuf[c].z, vbuf[c].w};
            union { __nv_bfloat16 b[4]; uint2 u; } nh, nl, rh, rl;
#pragma unroll
            for (int j = 0; j < 4; j++) {
                float vn = vv[j] * iv;
                __nv_bfloat16 h1 = __float2bfloat16(vn);
                nh.b[j] = h1;
                nl.b[j] = __float2bfloat16(vn - __bfloat162float(h1));
                __nv_bfloat16 h2 = __float2bfloat16(vv[j]);
                rh.b[j] = h2;
                rl.b[j] = __float2bfloat16(vv[j] - __bfloat162float(h2));
            }
            *(uint2*)(vnh + dst + 4 * c) = nh.u;
            *(uint2*)(vnl + dst + 4 * c) = nl.u;
            *(uint2*)(vh_ + dst + 4 * c) = rh.u;
            *(uint2*)(vl_ + dst + 4 * c) = rl.u;
        }
    } else {
        uint2 z = {0, 0};
#pragma unroll 4
        for (int c = 0; c < HD; c += 4) {
            *(uint2*)(vnh + dst + c) = z;
            *(uint2*)(vnl + dst + c) = z;
            *(uint2*)(vh_ + dst + c) = z;
            *(uint2*)(vl_ + dst + c) = z;
        }
    }
}

// ============================================================================
// Row-0 attention, k-free, COALESCED: warp-per-row everywhere.
// q0 = Wq x0 (fp32), u = Wk^T q0, s_j = u . x_j, PV from g_v.
// ============================================================================
__global__ __launch_bounds__(256) void row0_kernel(const float* __restrict__ x,
                                                   const float* __restrict__ w_qkv,
                                                   const float* __restrict__ v,
                                                   __nv_bfloat16* __restrict__ ohi,
                                                   __nv_bfloat16* __restrict__ olo)
{
    __shared__ float q0s[HD];
    __shared__ float us[DIM];
    __shared__ float sc[SEQ];
    __shared__ float red[256];
    __shared__ float part[4][HD];
    const int tid = threadIdx.x;
    const int lane = tid & 31, wid = tid >> 5;
    const int b = blockIdx.x / NH, h = blockIdx.x % NH;

    // ---- q0[d] = 0.125 * (Wq[h*64+d] . x0_b), warp per d (coalesced lanes)
    {
        const float4* xr4 = (const float4*)(x + (size_t)b * DIM);   // n=0 row
#pragma unroll 1
        for (int i = 0; i < 8; i++) {
            const int d = wid * 8 + i;
            const float4* wrow = (const float4*)(w_qkv + (size_t)(h * HD + d) * DIM);
            float acc = 0.f;
#pragma unroll
            for (int c = lane; c < DIM / 4; c += 32) {
                float4 wv = wrow[c];
                float4 xv = xr4[c];
                acc += wv.x * xv.x + wv.y * xv.y + wv.z * xv.z + wv.w * xv.w;
            }
            acc = warp_sum(acc);
            if (lane == 0) q0s[d] = 0.125f * acc;
        }
    }
    __syncthreads();

    // ---- u[k] = sum_d q0s[d] * Wk[h*64+d][k]  (coalesced over k)
    {
        const float* wk = w_qkv + ((size_t)DIM + h * HD) * DIM;
        for (int k = tid; k < DIM; k += 256) {
            float acc = 0.f;
#pragma unroll 8
            for (int dd = 0; dd < HD; dd++)
                acc += q0s[dd] * wk[(size_t)dd * DIM + k];
            us[k] = acc;
        }
    }
    __syncthreads();

    // ---- scores s_j = u . x_j : warp per row (coalesced lanes)
#pragma unroll 1
    for (int j = wid; j < SEQ; j += 8) {
        const float4* xr = (const float4*)(x + (size_t)(j * BATCH + b) * DIM);
        const float4* u4 = (const float4*)us;
        float acc = 0.f;
#pragma unroll
        for (int c = lane; c < DIM / 4; c += 32) {
            float4 t = xr[c];
            float4 u = u4[c];
            acc += u.x * t.x + u.y * t.y + u.z * t.z + u.w * t.w;
        }
        acc = warp_sum(acc);
        if (lane == 0) sc[j] = acc;
    }
    __syncthreads();

    // ---- softmax over sc
    float lmax = -1e30f;
    for (int j = tid; j < SEQ; j += 256) lmax = fmaxf(lmax, sc[j]);
    red[tid] = lmax; __syncthreads();
    for (int s = 128; s > 0; s >>= 1) {
        if (tid < s) red[tid] = fmaxf(red[tid], red[tid + s]);
        __syncthreads();
    }
    float mval = red[0];
    __syncthreads();

    float lsum = 0.f;
    for (int j = tid; j < SEQ; j += 256) {
        float p = __expf(sc[j] - mval);
        sc[j] = p;
        lsum += p;
    }
    red[tid] = lsum; __syncthreads();
    for (int s = 128; s > 0; s >>= 1) {
        if (tid < s) red[tid] += red[tid + s];
        __syncthreads();
    }
    float l = red[0];
    __syncthreads();

    // ---- PV (coalesced: threads 0-63 read consecutive d within a row)
    const int d = tid & 63, pi = tid >> 6;
    float acc = 0.f;
    const float* vbase = v + (size_t)(b * SEQ) * DIM + h * HD;
    for (int j = pi; j < SEQ; j += 4)
        acc += sc[j] * vbase[(size_t)j * DIM + d];
    part[pi][d] = acc;
    __syncthreads();
    if (tid < HD) {
        float s = (part[0][tid] + part[1][tid] + part[2][tid] + part[3][tid]) / l;
        const size_t o = (size_t)(b * SEQ) * DIM + h * HD + tid;
        __nv_bfloat16 hh = __float2bfloat16(s);
        ohi[o] = hh;
        olo[o] = __float2bfloat16(s - __bfloat162float(hh));
    }
}

// ============================================================================
// Fused FA2-style VV attention, rows 1..1024.
// S = (Qh+Ql)·Kh (2-pass); PV = Ph·Vh + Ph·Vl + Pl·Vh (3-pass).
// Writes bf16 hi/lo output directly.
// ============================================================================
__global__ __launch_bounds__(256, 1)
void vv_mma_kernel(const __nv_bfloat16* __restrict__ vnh, const __nv_bfloat16* __restrict__ vnl,
                   const __nv_bfloat16* __restrict__ vvh, const __nv_bfloat16* __restrict__ vvl,
                   __nv_bfloat16* __restrict__ ohi, __nv_bfloat16* __restrict__ olo)
{
    extern __shared__ __nv_bfloat16 sm[];
    __nv_bfloat16* sKh = sm;
    __nv_bfloat16* sVh = sm + 128 * SROW2;
    __nv_bfloat16* sVl = sm + 2 * 128 * SROW2;

    const int tid = threadIdx.x, lane = tid & 31, wid = tid >> 5;
    const int bh = blockIdx.y, qt = blockIdx.x;
    const int b = bh / NH, h = bh % NH;
    const int q0 = 1 + qt * 128;
    const size_t base = (size_t)bh * NKP * HD;

    const int ld_r = tid >> 1, ld_c = (tid & 1) * 32;

    // stage Q (hi -> sKh, lo -> sVh), extract fragments
    {
        const size_t g = base + (size_t)(q0 + ld_r) * HD + ld_c;
        uint4* dh = (uint4*)(sKh + ld_r * SROW2 + ld_c);
        uint4* dl = (uint4*)(sVh + ld_r * SROW2 + ld_c);
        const uint4* p1 = (const uint4*)(vnh + g);
        const uint4* p2 = (const uint4*)(vnl + g);
#pragma unroll
        for (int i = 0; i < 4; i++) { dh[i] = p1[i]; dl[i] = p2[i]; }
    }
    __syncthreads();
    uint32_t qh[4][4], ql[4][4];
    {
        const int a_r = wid * 16 + (lane & 7) + ((lane >> 3) & 1) * 8;
        const int a_k = (lane >> 4) * 8;
        const uint32_t ah = smem_u32(sKh) + (uint32_t)(a_r * SROW2 + a_k) * 2;
        const uint32_t al = smem_u32(sVh) + (uint32_t)(a_r * SROW2 + a_k) * 2;
#pragma unroll
        for (int kt = 0; kt < 4; kt++) {
            ldsm4(qh[kt], ah + kt * 16 * 2);
            ldsm4(ql[kt], al + kt * 16 * 2);
        }
    }
    __syncthreads();

    float oacc[8][4];
#pragma unroll
    for (int g = 0; g < 8; g++)
#pragma unroll
        for (int r = 0; r < 4; r++) oacc[g][r] = 0.f;
    float la = 0.f, lb = 0.f;

    const int b_n = (lane & 7) + (lane >> 4) * 8;
    const int b_k = ((lane >> 3) & 1) * 8;
    const int t_r = lane & 15, t_c = (lane >> 4) * 8;
    const uint32_t sKh_u = smem_u32(sKh);
    const uint32_t sVh_u = smem_u32(sVh);
    const uint32_t sVl_u = smem_u32(sVl);

#pragma unroll 1
    for (int ktile = 0; ktile < 9; ktile++) {
        {
            const size_t g = base + (size_t)(ktile * 128 + ld_r) * HD + ld_c;
            uint4* d1 = (uint4*)(sKh + ld_r * SROW2 + ld_c);
            uint4* d3 = (uint4*)(sVh + ld_r * SROW2 + ld_c);
            uint4* d4 = (uint4*)(sVl + ld_r * SROW2 + ld_c);
            const uint4* p1 = (const uint4*)(vnh + g);
            const uint4* p3 = (const uint4*)(vvh + g);
            const uint4* p4 = (const uint4*)(vvl + g);
#pragma unroll
            for (int i = 0; i < 4; i++) { d1[i] = p1[i]; d3[i] = p3[i]; d4[i] = p4[i]; }
        }
        __syncthreads();

        // scores: 2-pass (Qh + Ql) x Kh
        float p[16][4];
#pragma unroll
        for (int f = 0; f < 16; f++)
#pragma unroll
            for (int r = 0; r < 4; r++) p[f][r] = 0.f;

#pragma unroll
        for (int kt = 0; kt < 4; kt++) {
#pragma unroll
            for (int g = 0; g < 8; g++) {
                uint32_t kh_[4];
                const uint32_t off = (uint32_t)((g * 16 + b_n) * SROW2 + kt * 16 + b_k) * 2;
                ldsm4(kh_, sKh_u + off);
                mma16816(p[2*g],   qh[kt], kh_);
                mma16816(p[2*g],   ql[kt], kh_);
                mma16816(p[2*g+1], qh[kt], kh_ + 2);
                mma16816(p[2*g+1], ql[kt], kh_ + 2);
            }
        }

        // softmax probs (fixed max), accumulate l
#pragma unroll
        for (int f = 0; f < 16; f++) {
            float2 e0 = exp_poly2(make_float2(p[f][0], p[f][1]));
            float2 e1 = exp_poly2(make_float2(p[f][2], p[f][3]));
            p[f][0] = e0.x; p[f][1] = e0.y; p[f][2] = e1.x; p[f][3] = e1.y;
            la += e0.x + e0.y;
            lb += e1.x + e1.y;
        }

        // PV: 3-pass Ph·Vh + Ph·Vl + Pl·Vh
#pragma unroll
        for (int kt = 0; kt < 8; kt++) {
            uint32_t pah[4], pal[4];
            {
                const float* sA = p[2 * kt];
                const float* sB = p[2 * kt + 1];
                pah[0] = pack_bf16x2(sA[0], sA[1]);
                pah[1] = pack_bf16x2(sA[2], sA[3]);
                pah[2] = pack_bf16x2(sB[0], sB[1]);
                pah[3] = pack_bf16x2(sB[2], sB[3]);
#pragma unroll
                for (int r4 = 0; r4 < 4; r4++) {
                    float2 fh = unpack_bf16x2(pah[r4]);
                    const float* s = (r4 < 2) ? sA : sB;
                    const int o = (r4 & 1) * 2;
                    pal[r4] = pack_bf16x2(s[o] - fh.x, s[o + 1] - fh.y);
                }
            }
#pragma unroll
            for (int g = 0; g < 4; g++) {
                uint32_t vh_[4], vl_[4];
                const uint32_t off = (uint32_t)((kt * 16 + t_r) * SROW2 + g * 16 + t_c) * 2;
                ldsm4t(vh_, sVh_u + off);
                ldsm4t(vl_, sVl_u + off);
                mma16816(oacc[2*g],   pah, vh_);
                mma16816(oacc[2*g],   pah, vl_);
                mma16816(oacc[2*g],   pal, vh_);
                mma16816(oacc[2*g+1], pah, vh_ + 2);
                mma16816(oacc[2*g+1], pah, vl_ + 2);
                mma16816(oacc[2*g+1], pal, vh_ + 2);
            }
        }
        __syncthreads();
    }

    // l reduce + pad correction + hi/lo output
    la += __shfl_xor_sync(0xffffffffu, la, 1);
    la += __shfl_xor_sync(0xffffffffu, la, 2);
    lb += __shfl_xor_sync(0xffffffffu, lb, 1);
    lb += __shfl_xor_sync(0xffffffffu, lb, 2);
    float P0;
    {
        float t = -0.125f;
        float hh = fmaf(t, 1.f/24.f, 1.f/6.f);
        hh = fmaf(t, hh, 0.5f);
        hh = fmaf(t, hh, 1.f);
        hh = fmaf(t, hh, 1.f);
        P0 = hh;
    }
    la -= 127.f * P0;
    lb -= 127.f * P0;
    const float ia = 1.f / la, ib = 1.f / lb;

    const int row_a = q0 + wid * 16 + (lane >> 2);
    const int col0 = h * HD + (lane & 3) * 2;
    const size_t oa = (size_t)(b * SEQ + row_a) * DIM;
    const size_t ob = (size_t)(b * SEQ + row_a + 8) * DIM;
#pragma unroll
    for (int g = 0; g < 8; g++) {
        float x0 = oacc[g][0] * ia, x1 = oacc[g][1] * ia;
        float y0 = oacc[g][2] * ib, y1 = oacc[g][3] * ib;
        uint32_t xh = pack_bf16x2(x0, x1);
        uint32_t yh = pack_bf16x2(y0, y1);
        float2 fxh = unpack_bf16x2(xh);
        float2 fyh = unpack_bf16x2(yh);
        uint32_t xl = pack_bf16x2(x0 - fxh.x, x1 - fxh.y);
        uint32_t yl = pack_bf16x2(y0 - fyh.x, y1 - fyh.y);
        *(uint32_t*)(ohi + oa + col0 + g * 8) = xh;
        *(uint32_t*)(olo + oa + col0 + g * 8) = xl;
        *(uint32_t*)(ohi + ob + col0 + g * 8) = yh;
        *(uint32_t*)(olo + ob + col0 + g * 8) = yl;
    }
}

// ============================================================================
extern "C" void kernel_launch(void* const* d_in, const int* in_sizes, int n_in,
                              void* d_out, int out_size)
{
    const float* x      = (const float*)d_in[0];
    const float* w_qkv  = (const float*)d_in[1];
    const float* w_proj = (const float*)d_in[2];
    const float* b_proj = (const float*)d_in[3];
    float* out = (float*)d_out;

    float *p_v;
    cudaGetSymbolAddress((void**)&p_v, g_v);
    __nv_bfloat16 *p_xh, *p_xl, *p_wvh, *p_wvl, *p_oh, *p_ol, *p_wph, *p_wpl;
    __nv_bfloat16 *p_vnh, *p_vnl, *p_vhh, *p_vll;
    cudaGetSymbolAddress((void**)&p_xh,  g_x_hi);
    cudaGetSymbolAddress((void**)&p_xl,  g_x_lo);
    cudaGetSymbolAddress((void**)&p_wvh, g_wv_hi);
    cudaGetSymbolAddress((void**)&p_wvl, g_wv_lo);
    cudaGetSymbolAddress((void**)&p_oh,  g_o_hi);
    cudaGetSymbolAddress((void**)&p_ol,  g_o_lo);
    cudaGetSymbolAddress((void**)&p_wph, g_wp_hi);
    cudaGetSymbolAddress((void**)&p_wpl, g_wp_lo);
    cudaGetSymbolAddress((void**)&p_vnh, g_vn_hi);
    cudaGetSymbolAddress((void**)&p_vnl, g_vn_lo);
    cudaGetSymbolAddress((void**)&p_vhh, g_v_hi);
    cudaGetSymbolAddress((void**)&p_vll, g_v_lo);

    const int vv_smem = 3 * 128 * SROW2 * 2;   // 55296 bytes
    cudaFuncSetAttribute(vv_mma_kernel, cudaFuncAttributeMaxDynamicSharedMemorySize, vv_smem);
    cudaFuncSetAttribute(mma_gemm<0, DIM>, cudaFuncAttributeMaxDynamicSharedMemorySize, GEMM_SMEM);
    cudaFuncSetAttribute(mma_gemm<1, DIM>, cudaFuncAttributeMaxDynamicSharedMemorySize, GEMM_SMEM);

    // 0) bf16 hi/lo conversions: x, w_qkv rows 1536..2304 (v weights), w_proj
    {
        int n4x = M_ROWS * DIM / 4;
        cvt_kernel<<<(n4x + 255) / 256, 256>>>(x, p_xh, p_xl, n4x);
        int n4w = DIM * DIM / 4;
        cvt_kernel<<<(n4w + 255) / 256, 256>>>(w_qkv + (size_t)2 * DIM * DIM, p_wvh, p_wvl, n4w);
        cvt_kernel<<<(n4w + 255) / 256, 256>>>(w_proj, p_wph, p_wpl, n4w);
    }
    // 1) V GEMM (v only; k eliminated via u = Wk^T q0 trick) -> g_v
    {
        dim3 grid(DIM / 128, (M_ROWS + 127) / 128);
        mma_gemm<0, DIM><<<grid, 256, GEMM_SMEM>>>(p_xh, p_xl, p_wvh, p_wvl, nullptr, p_v);
    }
    // 2) prep (norm fused): vn/v bf16 hi/lo padded operands
    {
        int total = BHN * NKP;
        prep_kernel<<<(total + 255) / 256, 256>>>(p_v, p_vnh, p_vnl, p_vhh, p_vll);
    }
    // 3) row-0 QK attention (k-free, coalesced warp-per-row)
    row0_kernel<<<BHN, 256>>>(x, w_qkv, p_v, p_oh, p_ol);
    // 4) VV cosine attention rows 1..1024
    {
        dim3 grid(8, BHN);
        vv_mma_kernel<<<grid, 256, vv_smem>>>(p_vnh, p_vnl, p_vhh, p_vll, p_oh, p_ol);
    }
    // 5) proj GEMM + bias -> out
    {
        dim3 grid(DIM / 128, (M_ROWS + 127) / 128);
        mma_gemm<1, DIM><<<grid, 256, GEMM_SMEM>>>(p_oh, p_ol, p_wph, p_wpl, b_proj, out);
    }
}

// round 14
// speedup vs baseline: 1.1970x; 1.1629x over previous
#include <cuda_runtime.h>
#include <cuda_bf16.h>
#include <cstdint>

#define NH    12
#define HD    64
#define SEQ   1025
#define BATCH 8
#define DIM   768
#define M_ROWS (BATCH * SEQ)   /* 8200 */
#define BHN   (BATCH * NH)     /* 96 */
#define NKP   1152             /* keys padded to 9*128 */
#define SROW2 72               /* padded smem row (bf16) for 64-dim tiles */
#define SROW  40               /* padded smem row (bf16) for 32-wide k-chunks */

// ---------------- scratch (device globals: allocation-free) ----------------
__device__ float g_v[(size_t)M_ROWS * DIM];    // v only (k,q eliminated algebraically)
__device__ float g_u[(size_t)BHN * DIM];       // row0 score vectors u = Wk^T q0
__device__ float g_sc[(size_t)BHN * SEQ];      // row0 raw scores

__device__ __nv_bfloat16 g_x_hi[(size_t)M_ROWS * DIM];
__device__ __nv_bfloat16 g_x_lo[(size_t)M_ROWS * DIM];
__device__ __nv_bfloat16 g_wv_hi[(size_t)DIM * DIM];
__device__ __nv_bfloat16 g_wv_lo[(size_t)DIM * DIM];
__device__ __nv_bfloat16 g_o_hi[(size_t)M_ROWS * DIM];
__device__ __nv_bfloat16 g_o_lo[(size_t)M_ROWS * DIM];
__device__ __nv_bfloat16 g_wp_hi[(size_t)DIM * DIM];
__device__ __nv_bfloat16 g_wp_lo[(size_t)DIM * DIM];

// VV attention operands: [bh][1152][64] bf16, zero padded past row 1024
__device__ __nv_bfloat16 g_vn_hi[(size_t)BHN * NKP * HD];
__device__ __nv_bfloat16 g_v_hi[(size_t)BHN * NKP * HD];
__device__ __nv_bfloat16 g_v_lo[(size_t)BHN * NKP * HD];

// ---------------- helpers ----------------
__device__ __forceinline__ float2 ffma2(float2 a, float2 b, float2 c) {
    float2 d;
    asm("fma.rn.f32x2 %0, %1, %2, %3;"
        : "=l"(*(unsigned long long*)&d)
        : "l"(*(unsigned long long*)&a),
          "l"(*(unsigned long long*)&b),
          "l"(*(unsigned long long*)&c));
    return d;
}

__device__ __forceinline__ uint32_t smem_u32(const void* p) {
    uint32_t a;
    asm("{ .reg .u64 t; cvta.to.shared.u64 t, %1; cvt.u32.u64 %0, t; }"
        : "=r"(a) : "l"(p));
    return a;
}

__device__ __forceinline__ void ldsm4(uint32_t* r, uint32_t addr) {
    asm volatile("ldmatrix.sync.aligned.m8n8.x4.shared.b16 {%0,%1,%2,%3}, [%4];"
                 : "=r"(r[0]), "=r"(r[1]), "=r"(r[2]), "=r"(r[3]) : "r"(addr));
}
__device__ __forceinline__ void ldsm4t(uint32_t* r, uint32_t addr) {
    asm volatile("ldmatrix.sync.aligned.m8n8.x4.trans.shared.b16 {%0,%1,%2,%3}, [%4];"
                 : "=r"(r[0]), "=r"(r[1]), "=r"(r[2]), "=r"(r[3]) : "r"(addr));
}

__device__ __forceinline__ void mma16816(float* d, const uint32_t* a, const uint32_t* b) {
    asm volatile(
        "mma.sync.aligned.m16n8k16.row.col.f32.bf16.bf16.f32 "
        "{%0,%1,%2,%3}, {%4,%5,%6,%7}, {%8,%9}, {%0,%1,%2,%3};"
        : "+f"(d[0]), "+f"(d[1]), "+f"(d[2]), "+f"(d[3])
        : "r"(a[0]), "r"(a[1]), "r"(a[2]), "r"(a[3]), "r"(b[0]), "r"(b[1]));
}

__device__ __forceinline__ uint32_t pack_bf16x2(float lo, float hi) {
    uint32_t r;
    asm("cvt.rn.bf16x2.f32 %0, %1, %2;" : "=r"(r) : "f"(hi), "f"(lo));
    return r;
}
__device__ __forceinline__ float2 unpack_bf16x2(uint32_t u) {
    __nv_bfloat162 b = *reinterpret_cast<__nv_bfloat162*>(&u);
    return make_float2(__bfloat162float(b.x), __bfloat162float(b.y));
}

// cp.async 16B with zero-fill when !ok
__device__ __forceinline__ void cp16(uint32_t dst, const void* src, bool ok) {
    asm volatile("cp.async.cg.shared.global [%0], [%1], 16, %2;"
                 :: "r"(dst), "l"(src), "r"(ok ? 16u : 0u));
}
#define CP_COMMIT() asm volatile("cp.async.commit_group;" ::: "memory")
#define CP_WAIT1()  asm volatile("cp.async.wait_group 1;" ::: "memory")
#define CP_WAIT0()  asm volatile("cp.async.wait_group 0;" ::: "memory")

// exp(0.125*s - 0.125) for s in [-1,1]: deg-4 Taylor on t in [-0.25, 0]
__device__ __forceinline__ float2 exp_poly2(float2 s) {
    float2 t = ffma2(s, make_float2(0.125f, 0.125f), make_float2(-0.125f, -0.125f));
    float2 hh = ffma2(t, make_float2(1.f/24.f, 1.f/24.f), make_float2(1.f/6.f, 1.f/6.f));
    hh = ffma2(t, hh, make_float2(0.5f, 0.5f));
    hh = ffma2(t, hh, make_float2(1.f, 1.f));
    hh = ffma2(t, hh, make_float2(1.f, 1.f));
    return hh;
}

__device__ __forceinline__ float warp_sum(float v) {
    v += __shfl_xor_sync(0xffffffffu, v, 16);
    v += __shfl_xor_sync(0xffffffffu, v, 8);
    v += __shfl_xor_sync(0xffffffffu, v, 4);
    v += __shfl_xor_sync(0xffffffffu, v, 2);
    v += __shfl_xor_sync(0xffffffffu, v, 1);
    return v;
}

// ============================================================================
// fp32 -> bf16 hi/lo split
// ============================================================================
__global__ void cvt_kernel(const float* __restrict__ in,
                           __nv_bfloat16* __restrict__ hi,
                           __nv_bfloat16* __restrict__ lo, int n4)
{
    int i = blockIdx.x * blockDim.x + threadIdx.x;
    if (i >= n4) return;
    float4 v = ((const float4*)in)[i];
    float vv[4] = {v.x, v.y, v.z, v.w};
    union { __nv_bfloat16 b[4]; uint2 u; } ph, pl;
#pragma unroll
    for (int j = 0; j < 4; j++) {
        __nv_bfloat16 h = __float2bfloat16(vv[j]);
        ph.b[j] = h;
        pl.b[j] = __float2bfloat16(vv[j] - __bfloat162float(h));
    }
    ((uint2*)hi)[i] = ph.u;
    ((uint2*)lo)[i] = pl.u;
}

// ============================================================================
// mma.sync bf16 hi/lo GEMM: 256 thr, 8 warps, 64x32 warp tiles, cp.async
// double buffer.  Block 128x128, BK=32.  D += Ah*Bh + Ah*Bl + Al*Bh.
// ============================================================================
#define STG 5120                    /* 128*SROW elems per buffer */
#define GEMM_SMEM (8 * STG * 2)     /* 2 stages x 4 arrays = 81920 bytes */

template<int MODE, int NOUT>
__global__ __launch_bounds__(256, 2) void mma_gemm(
    const __nv_bfloat16* __restrict__ Ahi, const __nv_bfloat16* __restrict__ Alo,
    const __nv_bfloat16* __restrict__ Bhi, const __nv_bfloat16* __restrict__ Blo,
    const float* __restrict__ bias, float* __restrict__ C)
{
    extern __shared__ __nv_bfloat16 smg[];
    const uint32_t smB = smem_u32(smg);

    const int tid = threadIdx.x;
    const int lane = tid & 31, wid = tid >> 5;
    const int warp_m = wid & 1;
    const int warp_n = wid >> 1;
    const int bm = blockIdx.y * 128, bn = blockIdx.x * 128;

    const int lr = tid >> 1, lk = (tid & 1) * 16;
    const int am = bm + lr;
    const bool aok = (am < M_ROWS);
    int arow;
    if (MODE == 0) arow = (am % SEQ) * BATCH + (am / SEQ);
    else           arow = am;
    if (!aok) arow = 0;
    const size_t aoff = (size_t)arow * DIM + lk;
    const size_t boff = (size_t)(bn + lr) * DIM + lk;
    const uint32_t rowb = (uint32_t)(lr * SROW + lk) * 2;

    const int a_r = warp_m * 64 + (lane & 7) + ((lane >> 3) & 1) * 8;
    const int a_k = (lane >> 4) * 8;
    const uint32_t aoffb = (uint32_t)(a_r * SROW + a_k) * 2;
    const int b_n = warp_n * 32 + (lane & 7) + (lane >> 4) * 8;
    const int b_k = ((lane >> 3) & 1) * 8;
    const uint32_t boffb = (uint32_t)(b_n * SROW + b_k) * 2;

    float acc[4][4][4];
#pragma unroll
    for (int i = 0; i < 4; i++)
#pragma unroll
        for (int j = 0; j < 4; j++)
#pragma unroll
            for (int r = 0; r < 4; r++) acc[i][j][r] = 0.f;

#define LOAD_STAGE(ST, GK)                                                    \
    do {                                                                      \
        const uint32_t s0 = smB + (uint32_t)((ST) * 4) * (STG * 2) + rowb;    \
        cp16(s0 + 0 * (STG * 2),      Ahi + aoff + (GK),     aok);            \
        cp16(s0 + 0 * (STG * 2) + 16, Ahi + aoff + (GK) + 8, aok);            \
        cp16(s0 + 1 * (STG * 2),      Alo + aoff + (GK),     aok);            \
        cp16(s0 + 1 * (STG * 2) + 16, Alo + aoff + (GK) + 8, aok);            \
        cp16(s0 + 2 * (STG * 2),      Bhi + boff + (GK),     true);           \
        cp16(s0 + 2 * (STG * 2) + 16, Bhi + boff + (GK) + 8, true);           \
        cp16(s0 + 3 * (STG * 2),      Blo + boff + (GK),     true);           \
        cp16(s0 + 3 * (STG * 2) + 16, Blo + boff + (GK) + 8, true);           \
        CP_COMMIT();                                                          \
    } while (0)

    LOAD_STAGE(0, 0);

#pragma unroll 1
    for (int kc = 0; kc < DIM / 32; kc++) {
        const int st = kc & 1;
        if (kc < DIM / 32 - 1) {
            LOAD_STAGE(st ^ 1, (size_t)(kc + 1) * 32);
            CP_WAIT1();
        } else {
            CP_WAIT0();
        }
        __syncthreads();

        const uint32_t aAh = smB + (uint32_t)(st * 4 + 0) * (STG * 2) + aoffb;
        const uint32_t aAl = smB + (uint32_t)(st * 4 + 1) * (STG * 2) + aoffb;
        const uint32_t aBh = smB + (uint32_t)(st * 4 + 2) * (STG * 2) + boffb;
        const uint32_t aBl = smB + (uint32_t)(st * 4 + 3) * (STG * 2) + boffb;

#pragma unroll
        for (int kh = 0; kh < 2; kh++) {
            const uint32_t kb = kh * 32;
            uint32_t ah[4][4], al[4][4];
#pragma unroll
            for (int mi = 0; mi < 4; mi++) {
                ldsm4(ah[mi], aAh + mi * (16 * SROW * 2) + kb);
                ldsm4(al[mi], aAl + mi * (16 * SROW * 2) + kb);
            }
#pragma unroll
            for (int np = 0; np < 2; np++) {
                uint32_t bh2[4], bl2[4];
                ldsm4(bh2, aBh + np * (16 * SROW * 2) + kb);
                ldsm4(bl2, aBl + np * (16 * SROW * 2) + kb);
#pragma unroll
                for (int mi = 0; mi < 4; mi++) {
                    mma16816(acc[mi][2 * np],     ah[mi], bh2);
                    mma16816(acc[mi][2 * np],     ah[mi], bl2);
                    mma16816(acc[mi][2 * np],     al[mi], bh2);
                    mma16816(acc[mi][2 * np + 1], ah[mi], bh2 + 2);
                    mma16816(acc[mi][2 * np + 1], ah[mi], bl2 + 2);
                    mma16816(acc[mi][2 * np + 1], al[mi], bh2 + 2);
                }
            }
        }
        __syncthreads();
    }

    const int col0 = bn + warp_n * 32 + (lane & 3) * 2;
    const int row0 = bm + warp_m * 64 + (lane >> 2);
#pragma unroll
    for (int mi = 0; mi < 4; mi++) {
#pragma unroll
        for (int half = 0; half < 2; half++) {
            const int m = row0 + mi * 16 + half * 8;
            if (m >= M_ROWS) continue;
            size_t crow;
            if (MODE == 0) crow = (size_t)m * NOUT;
            else           crow = (size_t)((m % SEQ) * BATCH + (m / SEQ)) * NOUT;
#pragma unroll
            for (int nj = 0; nj < 4; nj++) {
                const int col = col0 + nj * 8;
                float2 o = make_float2(acc[mi][nj][2 * half], acc[mi][nj][2 * half + 1]);
                if (MODE == 1) {
                    float2 bv = *(const float2*)&bias[col];
                    o.x += bv.x; o.y += bv.y;
                }
                *(float2*)&C[crow + col] = o;
            }
        }
    }
}

// ============================================================================
// prep (norm fused): per (bh,row) write bf16 hi of vn = v*inv and hi/lo of
// raw v; zero-pad rows >= SEQ. (vn-lo no longer needed: 1-pass scores.)
// ============================================================================
__global__ void prep_kernel(const float* __restrict__ v,
                            __nv_bfloat16* __restrict__ vnh,
                            __nv_bfloat16* __restrict__ vh_, __nv_bfloat16* __restrict__ vl_)
{
    int idx = blockIdx.x * blockDim.x + threadIdx.x;
    if (idx >= BHN * NKP) return;
    const int bh = idx / NKP, row = idx % NKP;
    const int b = bh / NH, h = bh % NH;
    const size_t dst = (size_t)idx * HD;
    if (row < SEQ) {
        const float* src = v + (size_t)(b * SEQ + row) * DIM + h * HD;
        float4 vbuf[16];
        float acc = 0.f;
#pragma unroll
        for (int c = 0; c < 16; c++) {
            float4 t = *(const float4*)(src + 4 * c);
            vbuf[c] = t;
            acc += t.x * t.x + t.y * t.y + t.z * t.z + t.w * t.w;
        }
        const float iv = 1.f / fmaxf(sqrtf(acc), 1e-6f);
#pragma unroll 4
        for (int c = 0; c < 16; c++) {
            float vv[4] = {vbuf[c].x, vbuf[c].y, vbuf[c].z, vbuf[c].w};
            union { __nv_bfloat16 b[4]; uint2 u; } nh, rh, rl;
#pragma unroll
            for (int j = 0; j < 4; j++) {
                nh.b[j] = __float2bfloat16(vv[j] * iv);
                __nv_bfloat16 h2 = __float2bfloat16(vv[j]);
                rh.b[j] = h2;
                rl.b[j] = __float2bfloat16(vv[j] - __bfloat162float(h2));
            }
            *(uint2*)(vnh + dst + 4 * c) = nh.u;
            *(uint2*)(vh_ + dst + 4 * c) = rh.u;
            *(uint2*)(vl_ + dst + 4 * c) = rl.u;
        }
    } else {
        uint2 z = {0, 0};
#pragma unroll 4
        for (int c = 0; c < HD; c += 4) {
            *(uint2*)(vnh + dst + c) = z;
            *(uint2*)(vh_ + dst + c) = z;
            *(uint2*)(vl_ + dst + c) = z;
        }
    }
}

// ============================================================================
// row0 stage A: per (b,h) u = Wk^T (0.125 * Wq x0), exact fp32. 96 blocks.
// ============================================================================
__global__ __launch_bounds__(256) void u_kernel(const float* __restrict__ x,
                                                const float* __restrict__ w_qkv,
                                                float* __restrict__ u_out)
{
    __shared__ float q0s[HD];
    const int tid = threadIdx.x;
    const int lane = tid & 31, wid = tid >> 5;
    const int b = blockIdx.x / NH, h = blockIdx.x % NH;

    {
        const float4* xr4 = (const float4*)(x + (size_t)b * DIM);
#pragma unroll 1
        for (int i = 0; i < 8; i++) {
            const int d = wid * 8 + i;
            const float4* wrow = (const float4*)(w_qkv + (size_t)(h * HD + d) * DIM);
            float acc = 0.f;
#pragma unroll
            for (int c = lane; c < DIM / 4; c += 32) {
                float4 wv = wrow[c];
                float4 xv = xr4[c];
                acc += wv.x * xv.x + wv.y * xv.y + wv.z * xv.z + wv.w * xv.w;
            }
            acc = warp_sum(acc);
            if (lane == 0) q0s[d] = 0.125f * acc;
        }
    }
    __syncthreads();

    const float* wk = w_qkv + ((size_t)DIM + h * HD) * DIM;
    float* uo = u_out + (size_t)blockIdx.x * DIM;
    for (int k = tid; k < DIM; k += 256) {
        float acc = 0.f;
#pragma unroll 8
        for (int dd = 0; dd < HD; dd++)
            acc += q0s[dd] * wk[(size_t)dd * DIM + k];
        uo[k] = acc;
    }
}

// ============================================================================
// row0 stage B: scores for all 12 heads at once; x read once per batch-tile.
// grid (9 tiles, 8 batches), 256 thr.
// ============================================================================
__global__ __launch_bounds__(256) void score_kernel(const float* __restrict__ x,
                                                    const float* __restrict__ u_in,
                                                    float* __restrict__ sc_out)
{
    __shared__ float sU[NH * DIM];   // 36 KB
    const int tid = threadIdx.x;
    const int lane = tid & 31, wid = tid >> 5;
    const int tile = blockIdx.x, b = blockIdx.y;

    for (int i = tid; i < NH * DIM; i += 256)
        sU[i] = u_in[(size_t)b * NH * DIM + i];
    __syncthreads();

    const int j0 = tile * 128 + wid * 16;
#pragma unroll 1
    for (int r = 0; r < 16; r++) {
        const int j = j0 + r;
        if (j >= SEQ) break;
        const float4* xr = (const float4*)(x + (size_t)(j * BATCH + b) * DIM);
        float acc[NH];
#pragma unroll
        for (int h = 0; h < NH; h++) acc[h] = 0.f;
#pragma unroll 1
        for (int c = lane; c < DIM / 4; c += 32) {
            float4 xv = xr[c];
#pragma unroll
            for (int h = 0; h < NH; h++) {
                float4 uv = ((const float4*)(sU + h * DIM))[c];
                acc[h] += uv.x * xv.x + uv.y * xv.y + uv.z * xv.z + uv.w * xv.w;
            }
        }
#pragma unroll
        for (int h = 0; h < NH; h++) acc[h] = warp_sum(acc[h]);
        if (lane == 0) {
#pragma unroll
            for (int h = 0; h < NH; h++)
                sc_out[(size_t)(b * NH + h) * SEQ + j] = acc[h];
        }
    }
}

// ============================================================================
// row0 stage C: per (b,h) softmax + PV from g_v; writes bf16 hi/lo output.
// ============================================================================
__global__ __launch_bounds__(256) void softpv_kernel(const float* __restrict__ sc_in,
                                                     const float* __restrict__ v,
                                                     __nv_bfloat16* __restrict__ ohi,
                                                     __nv_bfloat16* __restrict__ olo)
{
    __shared__ float sc[SEQ];
    __shared__ float red[256];
    __shared__ float part[4][HD];
    const int tid = threadIdx.x;
    const int b = blockIdx.x / NH, h = blockIdx.x % NH;

    for (int j = tid; j < SEQ; j += 256)
        sc[j] = sc_in[(size_t)blockIdx.x * SEQ + j];
    __syncthreads();

    float lmax = -1e30f;
    for (int j = tid; j < SEQ; j += 256) lmax = fmaxf(lmax, sc[j]);
    red[tid] = lmax; __syncthreads();
    for (int s = 128; s > 0; s >>= 1) {
        if (tid < s) red[tid] = fmaxf(red[tid], red[tid + s]);
        __syncthreads();
    }
    float mval = red[0];
    __syncthreads();

    float lsum = 0.f;
    for (int j = tid; j < SEQ; j += 256) {
        float p = __expf(sc[j] - mval);
        sc[j] = p;
        lsum += p;
    }
    red[tid] = lsum; __syncthreads();
    for (int s = 128; s > 0; s >>= 1) {
        if (tid < s) red[tid] += red[tid + s];
        __syncthreads();
    }
    float l = red[0];
    __syncthreads();

    const int d = tid & 63, pi = tid >> 6;
    float acc = 0.f;
    const float* vbase = v + (size_t)(b * SEQ) * DIM + h * HD;
    for (int j = pi; j < SEQ; j += 4)
        acc += sc[j] * vbase[(size_t)j * DIM + d];
    part[pi][d] = acc;
    __syncthreads();
    if (tid < HD) {
        float s = (part[0][tid] + part[1][tid] + part[2][tid] + part[3][tid]) / l;
        const size_t o = (size_t)(b * SEQ) * DIM + h * HD + tid;
        __nv_bfloat16 hh = __float2bfloat16(s);
        ohi[o] = hh;
        olo[o] = __float2bfloat16(s - __bfloat162float(hh));
    }
}

// ============================================================================
// Fused FA2-style VV attention, rows 1..1024.
// S = Qh·Kh (1-pass bf16 — score error enters the exponent scaled by 0.125,
// so p error ~4e-5). PV = Ph·Vh + Ph·Vl + Pl·Vh (3-pass, V-lo required).
// ============================================================================
__global__ __launch_bounds__(256, 1)
void vv_mma_kernel(const __nv_bfloat16* __restrict__ vnh,
                   const __nv_bfloat16* __restrict__ vvh, const __nv_bfloat16* __restrict__ vvl,
                   __nv_bfloat16* __restrict__ ohi, __nv_bfloat16* __restrict__ olo)
{
    extern __shared__ __nv_bfloat16 sm[];
    __nv_bfloat16* sKh = sm;
    __nv_bfloat16* sVh = sm + 128 * SROW2;
    __nv_bfloat16* sVl = sm + 2 * 128 * SROW2;

    const int tid = threadIdx.x, lane = tid & 31, wid = tid >> 5;
    const int bh = blockIdx.y, qt = blockIdx.x;
    const int b = bh / NH, h = bh % NH;
    const int q0 = 1 + qt * 128;
    const size_t base = (size_t)bh * NKP * HD;

    const int ld_r = tid >> 1, ld_c = (tid & 1) * 32;

    // stage Q (hi only), extract fragments
    {
        const size_t g = base + (size_t)(q0 + ld_r) * HD + ld_c;
        uint4* dh = (uint4*)(sKh + ld_r * SROW2 + ld_c);
        const uint4* p1 = (const uint4*)(vnh + g);
#pragma unroll
        for (int i = 0; i < 4; i++) dh[i] = p1[i];
    }
    __syncthreads();
    uint32_t qh[4][4];
    {
        const int a_r = wid * 16 + (lane & 7) + ((lane >> 3) & 1) * 8;
        const int a_k = (lane >> 4) * 8;
        const uint32_t ah = smem_u32(sKh) + (uint32_t)(a_r * SROW2 + a_k) * 2;
#pragma unroll
        for (int kt = 0; kt < 4; kt++)
            ldsm4(qh[kt], ah + kt * 16 * 2);
    }
    __syncthreads();

    float oacc[8][4];
#pragma unroll
    for (int g = 0; g < 8; g++)
#pragma unroll
        for (int r = 0; r < 4; r++) oacc[g][r] = 0.f;
    float la = 0.f, lb = 0.f;

    const int b_n = (lane & 7) + (lane >> 4) * 8;
    const int b_k = ((lane >> 3) & 1) * 8;
    const int t_r = lane & 15, t_c = (lane >> 4) * 8;
    const uint32_t sKh_u = smem_u32(sKh);
    const uint32_t sVh_u = smem_u32(sVh);
    const uint32_t sVl_u = smem_u32(sVl);

#pragma unroll 1
    for (int ktile = 0; ktile < 9; ktile++) {
        {
            const size_t g = base + (size_t)(ktile * 128 + ld_r) * HD + ld_c;
            uint4* d1 = (uint4*)(sKh + ld_r * SROW2 + ld_c);
            uint4* d3 = (uint4*)(sVh + ld_r * SROW2 + ld_c);
            uint4* d4 = (uint4*)(sVl + ld_r * SROW2 + ld_c);
            const uint4* p1 = (const uint4*)(vnh + g);
            const uint4* p3 = (const uint4*)(vvh + g);
            const uint4* p4 = (const uint4*)(vvl + g);
#pragma unroll
            for (int i = 0; i < 4; i++) { d1[i] = p1[i]; d3[i] = p3[i]; d4[i] = p4[i]; }
        }
        __syncthreads();

        // scores: 1-pass Qh x Kh
        float p[16][4];
#pragma unroll
        for (int f = 0; f < 16; f++)
#pragma unroll
            for (int r = 0; r < 4; r++) p[f][r] = 0.f;

#pragma unroll
        for (int kt = 0; kt < 4; kt++) {
#pragma unroll
            for (int g = 0; g < 8; g++) {
                uint32_t kh_[4];
                const uint32_t off = (uint32_t)((g * 16 + b_n) * SROW2 + kt * 16 + b_k) * 2;
                ldsm4(kh_, sKh_u + off);
                mma16816(p[2*g],   qh[kt], kh_);
                mma16816(p[2*g+1], qh[kt], kh_ + 2);
            }
        }

        // softmax probs (fixed max), accumulate l
#pragma unroll
        for (int f = 0; f < 16; f++) {
            float2 e0 = exp_poly2(make_float2(p[f][0], p[f][1]));
            float2 e1 = exp_poly2(make_float2(p[f][2], p[f][3]));
            p[f][0] = e0.x; p[f][1] = e0.y; p[f][2] = e1.x; p[f][3] = e1.y;
            la += e0.x + e0.y;
            lb += e1.x + e1.y;
        }

        // PV: 3-pass Ph·Vh + Ph·Vl + Pl·Vh
#pragma unroll
        for (int kt = 0; kt < 8; kt++) {
            uint32_t pah[4], pal[4];
            {
                const float* sA = p[2 * kt];
                const float* sB = p[2 * kt + 1];
                pah[0] = pack_bf16x2(sA[0], sA[1]);
                pah[1] = pack_bf16x2(sA[2], sA[3]);
                pah[2] = pack_bf16x2(sB[0], sB[1]);
                pah[3] = pack_bf16x2(sB[2], sB[3]);
#pragma unroll
                for (int r4 = 0; r4 < 4; r4++) {
                    float2 fh = unpack_bf16x2(pah[r4]);
                    const float* s = (r4 < 2) ? sA : sB;
                    const int o = (r4 & 1) * 2;
                    pal[r4] = pack_bf16x2(s[o] - fh.x, s[o + 1] - fh.y);
                }
            }
#pragma unroll
            for (int g = 0; g < 4; g++) {
                uint32_t vh_[4], vl_[4];
                const uint32_t off = (uint32_t)((kt * 16 + t_r) * SROW2 + g * 16 + t_c) * 2;
                ldsm4t(vh_, sVh_u + off);
                ldsm4t(vl_, sVl_u + off);
                mma16816(oacc[2*g],   pah, vh_);
                mma16816(oacc[2*g],   pah, vl_);
                mma16816(oacc[2*g],   pal, vh_);
                mma16816(oacc[2*g+1], pah, vh_ + 2);
                mma16816(oacc[2*g+1], pah, vl_ + 2);
                mma16816(oacc[2*g+1], pal, vh_ + 2);
            }
        }
        __syncthreads();
    }

    // l reduce + pad correction + hi/lo output
    la += __shfl_xor_sync(0xffffffffu, la, 1);
    la += __shfl_xor_sync(0xffffffffu, la, 2);
    lb += __shfl_xor_sync(0xffffffffu, lb, 1);
    lb += __shfl_xor_sync(0xffffffffu, lb, 2);
    float P0;
    {
        float t = -0.125f;
        float hh = fmaf(t, 1.f/24.f, 1.f/6.f);
        hh = fmaf(t, hh, 0.5f);
        hh = fmaf(t, hh, 1.f);
        hh = fmaf(t, hh, 1.f);
        P0 = hh;
    }
    la -= 127.f * P0;
    lb -= 127.f * P0;
    const float ia = 1.f / la, ib = 1.f / lb;

    const int row_a = q0 + wid * 16 + (lane >> 2);
    const int col0 = h * HD + (lane & 3) * 2;
    const size_t oa = (size_t)(b * SEQ + row_a) * DIM;
    const size_t ob = (size_t)(b * SEQ + row_a + 8) * DIM;
#pragma unroll
    for (int g = 0; g < 8; g++) {
        float x0 = oacc[g][0] * ia, x1 = oacc[g][1] * ia;
        float y0 = oacc[g][2] * ib, y1 = oacc[g][3] * ib;
        uint32_t xh = pack_bf16x2(x0, x1);
        uint32_t yh = pack_bf16x2(y0, y1);
        float2 fxh = unpack_bf16x2(xh);
        float2 fyh = unpack_bf16x2(yh);
        uint32_t xl = pack_bf16x2(x0 - fxh.x, x1 - fxh.y);
        uint32_t yl = pack_bf16x2(y0 - fyh.x, y1 - fyh.y);
        *(uint32_t*)(ohi + oa + col0 + g * 8) = xh;
        *(uint32_t*)(olo + oa + col0 + g * 8) = xl;
        *(uint32_t*)(ohi + ob + col0 + g * 8) = yh;
        *(uint32_t*)(olo + ob + col0 + g * 8) = yl;
    }
}

// ============================================================================
extern "C" void kernel_launch(void* const* d_in, const int* in_sizes, int n_in,
                              void* d_out, int out_size)
{
    const float* x      = (const float*)d_in[0];
    const float* w_qkv  = (const float*)d_in[1];
    const float* w_proj = (const float*)d_in[2];
    const float* b_proj = (const float*)d_in[3];
    float* out = (float*)d_out;

    float *p_v, *p_u, *p_sc;
    cudaGetSymbolAddress((void**)&p_v,  g_v);
    cudaGetSymbolAddress((void**)&p_u,  g_u);
    cudaGetSymbolAddress((void**)&p_sc, g_sc);
    __nv_bfloat16 *p_xh, *p_xl, *p_wvh, *p_wvl, *p_oh, *p_ol, *p_wph, *p_wpl;
    __nv_bfloat16 *p_vnh, *p_vhh, *p_vll;
    cudaGetSymbolAddress((void**)&p_xh,  g_x_hi);
    cudaGetSymbolAddress((void**)&p_xl,  g_x_lo);
    cudaGetSymbolAddress((void**)&p_wvh, g_wv_hi);
    cudaGetSymbolAddress((void**)&p_wvl, g_wv_lo);
    cudaGetSymbolAddress((void**)&p_oh,  g_o_hi);
    cudaGetSymbolAddress((void**)&p_ol,  g_o_lo);
    cudaGetSymbolAddress((void**)&p_wph, g_wp_hi);
    cudaGetSymbolAddress((void**)&p_wpl, g_wp_lo);
    cudaGetSymbolAddress((void**)&p_vnh, g_vn_hi);
    cudaGetSymbolAddress((void**)&p_vhh, g_v_hi);
    cudaGetSymbolAddress((void**)&p_vll, g_v_lo);

    const int vv_smem = 3 * 128 * SROW2 * 2;   // 55296 bytes
    cudaFuncSetAttribute(vv_mma_kernel, cudaFuncAttributeMaxDynamicSharedMemorySize, vv_smem);
    cudaFuncSetAttribute(mma_gemm<0, DIM>, cudaFuncAttributeMaxDynamicSharedMemorySize, GEMM_SMEM);
    cudaFuncSetAttribute(mma_gemm<1, DIM>, cudaFuncAttributeMaxDynamicSharedMemorySize, GEMM_SMEM);

    // 0) bf16 hi/lo conversions: x, w_qkv rows 1536..2304 (v weights), w_proj
    {
        int n4x = M_ROWS * DIM / 4;
        cvt_kernel<<<(n4x + 255) / 256, 256>>>(x, p_xh, p_xl, n4x);
        int n4w = DIM * DIM / 4;
        cvt_kernel<<<(n4w + 255) / 256, 256>>>(w_qkv + (size_t)2 * DIM * DIM, p_wvh, p_wvl, n4w);
        cvt_kernel<<<(n4w + 255) / 256, 256>>>(w_proj, p_wph, p_wpl, n4w);
    }
    // 1) V GEMM -> g_v
    {
        dim3 grid(DIM / 128, (M_ROWS + 127) / 128);
        mma_gemm<0, DIM><<<grid, 256, GEMM_SMEM>>>(p_xh, p_xl, p_wvh, p_wvl, nullptr, p_v);
    }
    // 2) prep (norm fused): vn hi + v hi/lo padded operands
    {
        int total = BHN * NKP;
        prep_kernel<<<(total + 255) / 256, 256>>>(p_v, p_vnh, p_vhh, p_vll);
    }
    // 3) row0: u vectors, batched scores (x read once/batch), softmax+PV
    u_kernel<<<BHN, 256>>>(x, w_qkv, p_u);
    {
        dim3 grid(9, BATCH);
        score_kernel<<<grid, 256>>>(x, p_u, p_sc);
    }
    softpv_kernel<<<BHN, 256>>>(p_sc, p_v, p_oh, p_ol);
    // 4) VV cosine attention rows 1..1024 (1-pass S)
    {
        dim3 grid(8, BHN);
        vv_mma_kernel<<<grid, 256, vv_smem>>>(p_vnh, p_vhh, p_vll, p_oh, p_ol);
    }
    // 5) proj GEMM + bias -> out
    {
        dim3 grid(DIM / 128, (M_ROWS + 127) / 128);
        mma_gemm<1, DIM><<<grid, 256, GEMM_SMEM>>>(p_oh, p_ol, p_wph, p_wpl, b_proj, out);
    }
}

// round 15
// speedup vs baseline: 1.2304x; 1.0279x over previous
#include <cuda_runtime.h>
#include <cuda_bf16.h>
#include <cstdint>

#define NH    12
#define HD    64
#define SEQ   1025
#define BATCH 8
#define DIM   768
#define M_ROWS (BATCH * SEQ)   /* 8200 */
#define BHN   (BATCH * NH)     /* 96 */
#define NKP   1152             /* keys padded to 9*128 */
#define SROW2 72               /* padded smem row (bf16) for 64-dim tiles */
#define SROW  40               /* padded smem row (bf16) for 32-wide k-chunks */

// ---------------- scratch (device globals: allocation-free) ----------------
__device__ float g_v[(size_t)M_ROWS * DIM];    // v only (k,q eliminated algebraically)
__device__ float g_u[(size_t)BHN * DIM];       // row0 score vectors u = Wk^T q0
__device__ float g_sc[(size_t)BHN * SEQ];      // row0 raw scores

__device__ __nv_bfloat16 g_x_hi[(size_t)M_ROWS * DIM];
__device__ __nv_bfloat16 g_x_lo[(size_t)M_ROWS * DIM];
__device__ __nv_bfloat16 g_wv_hi[(size_t)DIM * DIM];
__device__ __nv_bfloat16 g_wv_lo[(size_t)DIM * DIM];
__device__ __nv_bfloat16 g_o_hi[(size_t)M_ROWS * DIM];
__device__ __nv_bfloat16 g_o_lo[(size_t)M_ROWS * DIM];
__device__ __nv_bfloat16 g_wp_hi[(size_t)DIM * DIM];
__device__ __nv_bfloat16 g_wp_lo[(size_t)DIM * DIM];

// VV attention operands: [bh][1152][64] bf16, zero padded past row 1024
__device__ __nv_bfloat16 g_vn_hi[(size_t)BHN * NKP * HD];
__device__ __nv_bfloat16 g_v_hi[(size_t)BHN * NKP * HD];
__device__ __nv_bfloat16 g_v_lo[(size_t)BHN * NKP * HD];

// ---------------- helpers ----------------
__device__ __forceinline__ float2 ffma2(float2 a, float2 b, float2 c) {
    float2 d;
    asm("fma.rn.f32x2 %0, %1, %2, %3;"
        : "=l"(*(unsigned long long*)&d)
        : "l"(*(unsigned long long*)&a),
          "l"(*(unsigned long long*)&b),
          "l"(*(unsigned long long*)&c));
    return d;
}

__device__ __forceinline__ uint32_t smem_u32(const void* p) {
    uint32_t a;
    asm("{ .reg .u64 t; cvta.to.shared.u64 t, %1; cvt.u32.u64 %0, t; }"
        : "=r"(a) : "l"(p));
    return a;
}

__device__ __forceinline__ void ldsm4(uint32_t* r, uint32_t addr) {
    asm volatile("ldmatrix.sync.aligned.m8n8.x4.shared.b16 {%0,%1,%2,%3}, [%4];"
                 : "=r"(r[0]), "=r"(r[1]), "=r"(r[2]), "=r"(r[3]) : "r"(addr));
}
__device__ __forceinline__ void ldsm4t(uint32_t* r, uint32_t addr) {
    asm volatile("ldmatrix.sync.aligned.m8n8.x4.trans.shared.b16 {%0,%1,%2,%3}, [%4];"
                 : "=r"(r[0]), "=r"(r[1]), "=r"(r[2]), "=r"(r[3]) : "r"(addr));
}

__device__ __forceinline__ void mma16816(float* d, const uint32_t* a, const uint32_t* b) {
    asm volatile(
        "mma.sync.aligned.m16n8k16.row.col.f32.bf16.bf16.f32 "
        "{%0,%1,%2,%3}, {%4,%5,%6,%7}, {%8,%9}, {%0,%1,%2,%3};"
        : "+f"(d[0]), "+f"(d[1]), "+f"(d[2]), "+f"(d[3])
        : "r"(a[0]), "r"(a[1]), "r"(a[2]), "r"(a[3]), "r"(b[0]), "r"(b[1]));
}

__device__ __forceinline__ uint32_t pack_bf16x2(float lo, float hi) {
    uint32_t r;
    asm("cvt.rn.bf16x2.f32 %0, %1, %2;" : "=r"(r) : "f"(hi), "f"(lo));
    return r;
}
__device__ __forceinline__ float2 unpack_bf16x2(uint32_t u) {
    __nv_bfloat162 b = *reinterpret_cast<__nv_bfloat162*>(&u);
    return make_float2(__bfloat162float(b.x), __bfloat162float(b.y));
}

// cp.async 16B with zero-fill when !ok
__device__ __forceinline__ void cp16(uint32_t dst, const void* src, bool ok) {
    asm volatile("cp.async.cg.shared.global [%0], [%1], 16, %2;"
                 :: "r"(dst), "l"(src), "r"(ok ? 16u : 0u));
}
#define CP_COMMIT() asm volatile("cp.async.commit_group;" ::: "memory")
#define CP_WAIT1()  asm volatile("cp.async.wait_group 1;" ::: "memory")
#define CP_WAIT0()  asm volatile("cp.async.wait_group 0;" ::: "memory")

// exp(0.125*s - 0.125) for s in [-1,1]: deg-4 Taylor on t in [-0.25, 0]
__device__ __forceinline__ float2 exp_poly2(float2 s) {
    float2 t = ffma2(s, make_float2(0.125f, 0.125f), make_float2(-0.125f, -0.125f));
    float2 hh = ffma2(t, make_float2(1.f/24.f, 1.f/24.f), make_float2(1.f/6.f, 1.f/6.f));
    hh = ffma2(t, hh, make_float2(0.5f, 0.5f));
    hh = ffma2(t, hh, make_float2(1.f, 1.f));
    hh = ffma2(t, hh, make_float2(1.f, 1.f));
    return hh;
}

__device__ __forceinline__ float warp_sum(float v) {
    v += __shfl_xor_sync(0xffffffffu, v, 16);
    v += __shfl_xor_sync(0xffffffffu, v, 8);
    v += __shfl_xor_sync(0xffffffffu, v, 4);
    v += __shfl_xor_sync(0xffffffffu, v, 2);
    v += __shfl_xor_sync(0xffffffffu, v, 1);
    return v;
}

// ============================================================================
// fp32 -> bf16 hi/lo split
// ============================================================================
__global__ void cvt_kernel(const float* __restrict__ in,
                           __nv_bfloat16* __restrict__ hi,
                           __nv_bfloat16* __restrict__ lo, int n4)
{
    int i = blockIdx.x * blockDim.x + threadIdx.x;
    if (i >= n4) return;
    float4 v = ((const float4*)in)[i];
    float vv[4] = {v.x, v.y, v.z, v.w};
    union { __nv_bfloat16 b[4]; uint2 u; } ph, pl;
#pragma unroll
    for (int j = 0; j < 4; j++) {
        __nv_bfloat16 h = __float2bfloat16(vv[j]);
        ph.b[j] = h;
        pl.b[j] = __float2bfloat16(vv[j] - __bfloat162float(h));
    }
    ((uint2*)hi)[i] = ph.u;
    ((uint2*)lo)[i] = pl.u;
}

// ============================================================================
// mma.sync bf16 hi/lo GEMM: 256 thr, 8 warps, 64x32 warp tiles, cp.async
// double buffer.  Block 128x128, BK=32.  D += Ah*Bh + Ah*Bl + Al*Bh.
// ============================================================================
#define STG 5120                    /* 128*SROW elems per buffer */
#define GEMM_SMEM (8 * STG * 2)     /* 2 stages x 4 arrays = 81920 bytes */

template<int MODE, int NOUT>
__global__ __launch_bounds__(256, 2) void mma_gemm(
    const __nv_bfloat16* __restrict__ Ahi, const __nv_bfloat16* __restrict__ Alo,
    const __nv_bfloat16* __restrict__ Bhi, const __nv_bfloat16* __restrict__ Blo,
    const float* __restrict__ bias, float* __restrict__ C)
{
    extern __shared__ __nv_bfloat16 smg[];
    const uint32_t smB = smem_u32(smg);

    const int tid = threadIdx.x;
    const int lane = tid & 31, wid = tid >> 5;
    const int warp_m = wid & 1;
    const int warp_n = wid >> 1;
    const int bm = blockIdx.y * 128, bn = blockIdx.x * 128;

    const int lr = tid >> 1, lk = (tid & 1) * 16;
    const int am = bm + lr;
    const bool aok = (am < M_ROWS);
    int arow;
    if (MODE == 0) arow = (am % SEQ) * BATCH + (am / SEQ);
    else           arow = am;
    if (!aok) arow = 0;
    const size_t aoff = (size_t)arow * DIM + lk;
    const size_t boff = (size_t)(bn + lr) * DIM + lk;
    const uint32_t rowb = (uint32_t)(lr * SROW + lk) * 2;

    const int a_r = warp_m * 64 + (lane & 7) + ((lane >> 3) & 1) * 8;
    const int a_k = (lane >> 4) * 8;
    const uint32_t aoffb = (uint32_t)(a_r * SROW + a_k) * 2;
    const int b_n = warp_n * 32 + (lane & 7) + (lane >> 4) * 8;
    const int b_k = ((lane >> 3) & 1) * 8;
    const uint32_t boffb = (uint32_t)(b_n * SROW + b_k) * 2;

    float acc[4][4][4];
#pragma unroll
    for (int i = 0; i < 4; i++)
#pragma unroll
        for (int j = 0; j < 4; j++)
#pragma unroll
            for (int r = 0; r < 4; r++) acc[i][j][r] = 0.f;

#define LOAD_STAGE(ST, GK)                                                    \
    do {                                                                      \
        const uint32_t s0 = smB + (uint32_t)((ST) * 4) * (STG * 2) + rowb;    \
        cp16(s0 + 0 * (STG * 2),      Ahi + aoff + (GK),     aok);            \
        cp16(s0 + 0 * (STG * 2) + 16, Ahi + aoff + (GK) + 8, aok);            \
        cp16(s0 + 1 * (STG * 2),      Alo + aoff + (GK),     aok);            \
        cp16(s0 + 1 * (STG * 2) + 16, Alo + aoff + (GK) + 8, aok);            \
        cp16(s0 + 2 * (STG * 2),      Bhi + boff + (GK),     true);           \
        cp16(s0 + 2 * (STG * 2) + 16, Bhi + boff + (GK) + 8, true);           \
        cp16(s0 + 3 * (STG * 2),      Blo + boff + (GK),     true);           \
        cp16(s0 + 3 * (STG * 2) + 16, Blo + boff + (GK) + 8, true);           \
        CP_COMMIT();                                                          \
    } while (0)

    LOAD_STAGE(0, 0);

#pragma unroll 1
    for (int kc = 0; kc < DIM / 32; kc++) {
        const int st = kc & 1;
        if (kc < DIM / 32 - 1) {
            LOAD_STAGE(st ^ 1, (size_t)(kc + 1) * 32);
            CP_WAIT1();
        } else {
            CP_WAIT0();
        }
        __syncthreads();

        const uint32_t aAh = smB + (uint32_t)(st * 4 + 0) * (STG * 2) + aoffb;
        const uint32_t aAl = smB + (uint32_t)(st * 4 + 1) * (STG * 2) + aoffb;
        const uint32_t aBh = smB + (uint32_t)(st * 4 + 2) * (STG * 2) + boffb;
        const uint32_t aBl = smB + (uint32_t)(st * 4 + 3) * (STG * 2) + boffb;

#pragma unroll
        for (int kh = 0; kh < 2; kh++) {
            const uint32_t kb = kh * 32;
            uint32_t ah[4][4], al[4][4];
#pragma unroll
            for (int mi = 0; mi < 4; mi++) {
                ldsm4(ah[mi], aAh + mi * (16 * SROW * 2) + kb);
                ldsm4(al[mi], aAl + mi * (16 * SROW * 2) + kb);
            }
#pragma unroll
            for (int np = 0; np < 2; np++) {
                uint32_t bh2[4], bl2[4];
                ldsm4(bh2, aBh + np * (16 * SROW * 2) + kb);
                ldsm4(bl2, aBl + np * (16 * SROW * 2) + kb);
#pragma unroll
                for (int mi = 0; mi < 4; mi++) {
                    mma16816(acc[mi][2 * np],     ah[mi], bh2);
                    mma16816(acc[mi][2 * np],     ah[mi], bl2);
                    mma16816(acc[mi][2 * np],     al[mi], bh2);
                    mma16816(acc[mi][2 * np + 1], ah[mi], bh2 + 2);
                    mma16816(acc[mi][2 * np + 1], ah[mi], bl2 + 2);
                    mma16816(acc[mi][2 * np + 1], al[mi], bh2 + 2);
                }
            }
        }
        __syncthreads();
    }

    const int col0 = bn + warp_n * 32 + (lane & 3) * 2;
    const int row0 = bm + warp_m * 64 + (lane >> 2);
#pragma unroll
    for (int mi = 0; mi < 4; mi++) {
#pragma unroll
        for (int half = 0; half < 2; half++) {
            const int m = row0 + mi * 16 + half * 8;
            if (m >= M_ROWS) continue;
            size_t crow;
            if (MODE == 0) crow = (size_t)m * NOUT;
            else           crow = (size_t)((m % SEQ) * BATCH + (m / SEQ)) * NOUT;
#pragma unroll
            for (int nj = 0; nj < 4; nj++) {
                const int col = col0 + nj * 8;
                float2 o = make_float2(acc[mi][nj][2 * half], acc[mi][nj][2 * half + 1]);
                if (MODE == 1) {
                    float2 bv = *(const float2*)&bias[col];
                    o.x += bv.x; o.y += bv.y;
                }
                *(float2*)&C[crow + col] = o;
            }
        }
    }
}

// ============================================================================
// prep (norm fused): per (bh,row) write bf16 hi of vn = v*inv and hi/lo of
// raw v; zero-pad rows >= SEQ.
// ============================================================================
__global__ void prep_kernel(const float* __restrict__ v,
                            __nv_bfloat16* __restrict__ vnh,
                            __nv_bfloat16* __restrict__ vh_, __nv_bfloat16* __restrict__ vl_)
{
    int idx = blockIdx.x * blockDim.x + threadIdx.x;
    if (idx >= BHN * NKP) return;
    const int bh = idx / NKP, row = idx % NKP;
    const int b = bh / NH, h = bh % NH;
    const size_t dst = (size_t)idx * HD;
    if (row < SEQ) {
        const float* src = v + (size_t)(b * SEQ + row) * DIM + h * HD;
        float4 vbuf[16];
        float acc = 0.f;
#pragma unroll
        for (int c = 0; c < 16; c++) {
            float4 t = *(const float4*)(src + 4 * c);
            vbuf[c] = t;
            acc += t.x * t.x + t.y * t.y + t.z * t.z + t.w * t.w;
        }
        const float iv = 1.f / fmaxf(sqrtf(acc), 1e-6f);
#pragma unroll 4
        for (int c = 0; c < 16; c++) {
            float vv[4] = {vbuf[c].x, vbuf[c].y, vbuf[c].z, vbuf[c].w};
            union { __nv_bfloat16 b[4]; uint2 u; } nh, rh, rl;
#pragma unroll
            for (int j = 0; j < 4; j++) {
                nh.b[j] = __float2bfloat16(vv[j] * iv);
                __nv_bfloat16 h2 = __float2bfloat16(vv[j]);
                rh.b[j] = h2;
                rl.b[j] = __float2bfloat16(vv[j] - __bfloat162float(h2));
            }
            *(uint2*)(vnh + dst + 4 * c) = nh.u;
            *(uint2*)(vh_ + dst + 4 * c) = rh.u;
            *(uint2*)(vl_ + dst + 4 * c) = rl.u;
        }
    } else {
        uint2 z = {0, 0};
#pragma unroll 4
        for (int c = 0; c < HD; c += 4) {
            *(uint2*)(vnh + dst + c) = z;
            *(uint2*)(vh_ + dst + c) = z;
            *(uint2*)(vl_ + dst + c) = z;
        }
    }
}

// ============================================================================
// row0 stage A: per (b,h) u = Wk^T (0.125 * Wq x0), exact fp32. 96 blocks.
// ============================================================================
__global__ __launch_bounds__(256) void u_kernel(const float* __restrict__ x,
                                                const float* __restrict__ w_qkv,
                                                float* __restrict__ u_out)
{
    __shared__ float q0s[HD];
    const int tid = threadIdx.x;
    const int lane = tid & 31, wid = tid >> 5;
    const int b = blockIdx.x / NH, h = blockIdx.x % NH;

    {
        const float4* xr4 = (const float4*)(x + (size_t)b * DIM);
#pragma unroll 1
        for (int i = 0; i < 8; i++) {
            const int d = wid * 8 + i;
            const float4* wrow = (const float4*)(w_qkv + (size_t)(h * HD + d) * DIM);
            float acc = 0.f;
#pragma unroll
            for (int c = lane; c < DIM / 4; c += 32) {
                float4 wv = wrow[c];
                float4 xv = xr4[c];
                acc += wv.x * xv.x + wv.y * xv.y + wv.z * xv.z + wv.w * xv.w;
            }
            acc = warp_sum(acc);
            if (lane == 0) q0s[d] = 0.125f * acc;
        }
    }
    __syncthreads();

    const float* wk = w_qkv + ((size_t)DIM + h * HD) * DIM;
    float* uo = u_out + (size_t)blockIdx.x * DIM;
    for (int k = tid; k < DIM; k += 256) {
        float acc = 0.f;
#pragma unroll 8
        for (int dd = 0; dd < HD; dd++)
            acc += q0s[dd] * wk[(size_t)dd * DIM + k];
        uo[k] = acc;
    }
}

// ============================================================================
// row0 stage B: scores for all 12 heads at once; x read once per batch-tile.
// ============================================================================
__global__ __launch_bounds__(256) void score_kernel(const float* __restrict__ x,
                                                    const float* __restrict__ u_in,
                                                    float* __restrict__ sc_out)
{
    __shared__ float sU[NH * DIM];   // 36 KB
    const int tid = threadIdx.x;
    const int lane = tid & 31, wid = tid >> 5;
    const int tile = blockIdx.x, b = blockIdx.y;

    for (int i = tid; i < NH * DIM; i += 256)
        sU[i] = u_in[(size_t)b * NH * DIM + i];
    __syncthreads();

    const int j0 = tile * 128 + wid * 16;
#pragma unroll 1
    for (int r = 0; r < 16; r++) {
        const int j = j0 + r;
        if (j >= SEQ) break;
        const float4* xr = (const float4*)(x + (size_t)(j * BATCH + b) * DIM);
        float acc[NH];
#pragma unroll
        for (int h = 0; h < NH; h++) acc[h] = 0.f;
#pragma unroll 1
        for (int c = lane; c < DIM / 4; c += 32) {
            float4 xv = xr[c];
#pragma unroll
            for (int h = 0; h < NH; h++) {
                float4 uv = ((const float4*)(sU + h * DIM))[c];
                acc[h] += uv.x * xv.x + uv.y * xv.y + uv.z * xv.z + uv.w * xv.w;
            }
        }
#pragma unroll
        for (int h = 0; h < NH; h++) acc[h] = warp_sum(acc[h]);
        if (lane == 0) {
#pragma unroll
            for (int h = 0; h < NH; h++)
                sc_out[(size_t)(b * NH + h) * SEQ + j] = acc[h];
        }
    }
}

// ============================================================================
// row0 stage C: per (b,h) softmax + PV from g_v; writes bf16 hi/lo output.
// ============================================================================
__global__ __launch_bounds__(256) void softpv_kernel(const float* __restrict__ sc_in,
                                                     const float* __restrict__ v,
                                                     __nv_bfloat16* __restrict__ ohi,
                                                     __nv_bfloat16* __restrict__ olo)
{
    __shared__ float sc[SEQ];
    __shared__ float red[256];
    __shared__ float part[4][HD];
    const int tid = threadIdx.x;
    const int b = blockIdx.x / NH, h = blockIdx.x % NH;

    for (int j = tid; j < SEQ; j += 256)
        sc[j] = sc_in[(size_t)blockIdx.x * SEQ + j];
    __syncthreads();

    float lmax = -1e30f;
    for (int j = tid; j < SEQ; j += 256) lmax = fmaxf(lmax, sc[j]);
    red[tid] = lmax; __syncthreads();
    for (int s = 128; s > 0; s >>= 1) {
        if (tid < s) red[tid] = fmaxf(red[tid], red[tid + s]);
        __syncthreads();
    }
    float mval = red[0];
    __syncthreads();

    float lsum = 0.f;
    for (int j = tid; j < SEQ; j += 256) {
        float p = __expf(sc[j] - mval);
        sc[j] = p;
        lsum += p;
    }
    red[tid] = lsum; __syncthreads();
    for (int s = 128; s > 0; s >>= 1) {
        if (tid < s) red[tid] += red[tid + s];
        __syncthreads();
    }
    float l = red[0];
    __syncthreads();

    const int d = tid & 63, pi = tid >> 6;
    float acc = 0.f;
    const float* vbase = v + (size_t)(b * SEQ) * DIM + h * HD;
    for (int j = pi; j < SEQ; j += 4)
        acc += sc[j] * vbase[(size_t)j * DIM + d];
    part[pi][d] = acc;
    __syncthreads();
    if (tid < HD) {
        float s = (part[0][tid] + part[1][tid] + part[2][tid] + part[3][tid]) / l;
        const size_t o = (size_t)(b * SEQ) * DIM + h * HD + tid;
        __nv_bfloat16 hh = __float2bfloat16(s);
        ohi[o] = hh;
        olo[o] = __float2bfloat16(s - __bfloat162float(hh));
    }
}

// ============================================================================
// Fused FA2-style VV attention, rows 1..1024, cp.async DOUBLE-BUFFERED tiles.
// S = Qh·Kh (1-pass); PV = Ph·Vh + Ph·Vl + Pl·Vh (3-pass).
// ============================================================================
#define VVT (3 * 128 * SROW2)             /* bf16 elems per stage */
#define VV_SMEM (2 * VVT * 2)             /* 110592 bytes */

__global__ __launch_bounds__(256, 1)
void vv_mma_kernel(const __nv_bfloat16* __restrict__ vnh,
                   const __nv_bfloat16* __restrict__ vvh, const __nv_bfloat16* __restrict__ vvl,
                   __nv_bfloat16* __restrict__ ohi, __nv_bfloat16* __restrict__ olo)
{
    extern __shared__ __nv_bfloat16 sm[];
    const uint32_t smB = smem_u32(sm);

    const int tid = threadIdx.x, lane = tid & 31, wid = tid >> 5;
    const int bh = blockIdx.y, qt = blockIdx.x;
    const int b = bh / NH, h = bh % NH;
    const int q0 = 1 + qt * 128;
    const size_t base = (size_t)bh * NKP * HD;

    const int ld_r = tid >> 1, ld_c = (tid & 1) * 32;
    const uint32_t ld_sm = (uint32_t)(ld_r * SROW2 + ld_c) * 2;   // byte offset in a tile
    const size_t   ld_g0 = (size_t)ld_r * HD + ld_c;

    // stage byte bases: stage s tile {K,Vh,Vl}
#define SK(s)  (smB + (uint32_t)(s) * (VVT * 2))
#define SVH(s) (SK(s) + 128 * SROW2 * 2)
#define SVL(s) (SK(s) + 2 * 128 * SROW2 * 2)

    // issue tile loads (cp.async) into stage s
#define VV_ISSUE(s, kt)                                                        \
    do {                                                                       \
        const size_t g = base + (size_t)(kt) * 128 * HD + ld_g0;               \
        const uint32_t dK = SK(s) + ld_sm, dH = SVH(s) + ld_sm, dL = SVL(s) + ld_sm; \
        cp16(dK + 0,  vnh + g,      true); cp16(dK + 16, vnh + g + 8,  true);  \
        cp16(dK + 32, vnh + g + 16, true); cp16(dK + 48, vnh + g + 24, true);  \
        cp16(dH + 0,  vvh + g,      true); cp16(dH + 16, vvh + g + 8,  true);  \
        cp16(dH + 32, vvh + g + 16, true); cp16(dH + 48, vvh + g + 24, true);  \
        cp16(dL + 0,  vvl + g,      true); cp16(dL + 16, vvl + g + 8,  true);  \
        cp16(dL + 32, vvl + g + 16, true); cp16(dL + 48, vvl + g + 24, true);  \
        CP_COMMIT();                                                           \
    } while (0)

    // prologue: start tile 0 into stage 0 immediately
    VV_ISSUE(0, 0);

    // stage Q (hi) into stage-1 K buffer via regular loads; extract fragments
    {
        const size_t g = base + (size_t)(q0 + ld_r) * HD + ld_c;
        uint4* dh = (uint4*)((char*)sm + (VVT * 2) + (ld_r * SROW2 + ld_c) * 2);
        const uint4* p1 = (const uint4*)(vnh + g);
#pragma unroll
        for (int i = 0; i < 4; i++) dh[i] = p1[i];
    }
    __syncthreads();
    uint32_t qh[4][4];
    {
        const int a_r = wid * 16 + (lane & 7) + ((lane >> 3) & 1) * 8;
        const int a_k = (lane >> 4) * 8;
        const uint32_t ah = SK(1) + (uint32_t)(a_r * SROW2 + a_k) * 2;
#pragma unroll
        for (int kt = 0; kt < 4; kt++)
            ldsm4(qh[kt], ah + kt * 16 * 2);
    }

    float oacc[8][4];
#pragma unroll
    for (int g = 0; g < 8; g++)
#pragma unroll
        for (int r = 0; r < 4; r++) oacc[g][r] = 0.f;
    float la = 0.f, lb = 0.f;

    const int b_n = (lane & 7) + (lane >> 4) * 8;
    const int b_k = ((lane >> 3) & 1) * 8;
    const int t_r = lane & 15, t_c = (lane >> 4) * 8;

#pragma unroll 1
    for (int ktile = 0; ktile < 9; ktile++) {
        const int st = ktile & 1;
        CP_WAIT0();            // current tile's group complete
        __syncthreads();       // all warps past previous compute + data visible
        if (ktile < 8) VV_ISSUE(st ^ 1, ktile + 1);   // overlap next load w/ compute

        const uint32_t sKh_u = SK(st), sVh_u = SVH(st), sVl_u = SVL(st);

        // scores: 1-pass Qh x Kh
        float p[16][4];
#pragma unroll
        for (int f = 0; f < 16; f++)
#pragma unroll
            for (int r = 0; r < 4; r++) p[f][r] = 0.f;

#pragma unroll
        for (int kt = 0; kt < 4; kt++) {
#pragma unroll
            for (int g = 0; g < 8; g++) {
                uint32_t kh_[4];
                const uint32_t off = (uint32_t)((g * 16 + b_n) * SROW2 + kt * 16 + b_k) * 2;
                ldsm4(kh_, sKh_u + off);
                mma16816(p[2*g],   qh[kt], kh_);
                mma16816(p[2*g+1], qh[kt], kh_ + 2);
            }
        }

        // softmax probs (fixed max), accumulate l
#pragma unroll
        for (int f = 0; f < 16; f++) {
            float2 e0 = exp_poly2(make_float2(p[f][0], p[f][1]));
            float2 e1 = exp_poly2(make_float2(p[f][2], p[f][3]));
            p[f][0] = e0.x; p[f][1] = e0.y; p[f][2] = e1.x; p[f][3] = e1.y;
            la += e0.x + e0.y;
            lb += e1.x + e1.y;
        }

        // PV: 3-pass Ph·Vh + Ph·Vl + Pl·Vh
#pragma unroll
        for (int kt = 0; kt < 8; kt++) {
            uint32_t pah[4], pal[4];
            {
                const float* sA = p[2 * kt];
                const float* sB = p[2 * kt + 1];
                pah[0] = pack_bf16x2(sA[0], sA[1]);
                pah[1] = pack_bf16x2(sA[2], sA[3]);
                pah[2] = pack_bf16x2(sB[0], sB[1]);
                pah[3] = pack_bf16x2(sB[2], sB[3]);
#pragma unroll
                for (int r4 = 0; r4 < 4; r4++) {
                    float2 fh = unpack_bf16x2(pah[r4]);
                    const float* s = (r4 < 2) ? sA : sB;
                    const int o = (r4 & 1) * 2;
                    pal[r4] = pack_bf16x2(s[o] - fh.x, s[o + 1] - fh.y);
                }
            }
#pragma unroll
            for (int g = 0; g < 4; g++) {
                uint32_t vh_[4], vl_[4];
                const uint32_t off = (uint32_t)((kt * 16 + t_r) * SROW2 + g * 16 + t_c) * 2;
                ldsm4t(vh_, sVh_u + off);
                ldsm4t(vl_, sVl_u + off);
                mma16816(oacc[2*g],   pah, vh_);
                mma16816(oacc[2*g],   pah, vl_);
                mma16816(oacc[2*g],   pal, vh_);
                mma16816(oacc[2*g+1], pah, vh_ + 2);
                mma16816(oacc[2*g+1], pah, vl_ + 2);
                mma16816(oacc[2*g+1], pal, vh_ + 2);
            }
        }
    }

    // l reduce + pad correction + hi/lo output
    la += __shfl_xor_sync(0xffffffffu, la, 1);
    la += __shfl_xor_sync(0xffffffffu, la, 2);
    lb += __shfl_xor_sync(0xffffffffu, lb, 1);
    lb += __shfl_xor_sync(0xffffffffu, lb, 2);
    float P0;
    {
        float t = -0.125f;
        float hh = fmaf(t, 1.f/24.f, 1.f/6.f);
        hh = fmaf(t, hh, 0.5f);
        hh = fmaf(t, hh, 1.f);
        hh = fmaf(t, hh, 1.f);
        P0 = hh;
    }
    la -= 127.f * P0;
    lb -= 127.f * P0;
    const float ia = 1.f / la, ib = 1.f / lb;

    const int row_a = q0 + wid * 16 + (lane >> 2);
    const int col0 = h * HD + (lane & 3) * 2;
    const size_t oa = (size_t)(b * SEQ + row_a) * DIM;
    const size_t ob = (size_t)(b * SEQ + row_a + 8) * DIM;
#pragma unroll
    for (int g = 0; g < 8; g++) {
        float x0 = oacc[g][0] * ia, x1 = oacc[g][1] * ia;
        float y0 = oacc[g][2] * ib, y1 = oacc[g][3] * ib;
        uint32_t xh = pack_bf16x2(x0, x1);
        uint32_t yh = pack_bf16x2(y0, y1);
        float2 fxh = unpack_bf16x2(xh);
        float2 fyh = unpack_bf16x2(yh);
        uint32_t xl = pack_bf16x2(x0 - fxh.x, x1 - fxh.y);
        uint32_t yl = pack_bf16x2(y0 - fyh.x, y1 - fyh.y);
        *(uint32_t*)(ohi + oa + col0 + g * 8) = xh;
        *(uint32_t*)(olo + oa + col0 + g * 8) = xl;
        *(uint32_t*)(ohi + ob + col0 + g * 8) = yh;
        *(uint32_t*)(olo + ob + col0 + g * 8) = yl;
    }
}

// ============================================================================
extern "C" void kernel_launch(void* const* d_in, const int* in_sizes, int n_in,
                              void* d_out, int out_size)
{
    const float* x      = (const float*)d_in[0];
    const float* w_qkv  = (const float*)d_in[1];
    const float* w_proj = (const float*)d_in[2];
    const float* b_proj = (const float*)d_in[3];
    float* out = (float*)d_out;

    float *p_v, *p_u, *p_sc;
    cudaGetSymbolAddress((void**)&p_v,  g_v);
    cudaGetSymbolAddress((void**)&p_u,  g_u);
    cudaGetSymbolAddress((void**)&p_sc, g_sc);
    __nv_bfloat16 *p_xh, *p_xl, *p_wvh, *p_wvl, *p_oh, *p_ol, *p_wph, *p_wpl;
    __nv_bfloat16 *p_vnh, *p_vhh, *p_vll;
    cudaGetSymbolAddress((void**)&p_xh,  g_x_hi);
    cudaGetSymbolAddress((void**)&p_xl,  g_x_lo);
    cudaGetSymbolAddress((void**)&p_wvh, g_wv_hi);
    cudaGetSymbolAddress((void**)&p_wvl, g_wv_lo);
    cudaGetSymbolAddress((void**)&p_oh,  g_o_hi);
    cudaGetSymbolAddress((void**)&p_ol,  g_o_lo);
    cudaGetSymbolAddress((void**)&p_wph, g_wp_hi);
    cudaGetSymbolAddress((void**)&p_wpl, g_wp_lo);
    cudaGetSymbolAddress((void**)&p_vnh, g_vn_hi);
    cudaGetSymbolAddress((void**)&p_vhh, g_v_hi);
    cudaGetSymbolAddress((void**)&p_vll, g_v_lo);

    cudaFuncSetAttribute(vv_mma_kernel, cudaFuncAttributeMaxDynamicSharedMemorySize, VV_SMEM);
    cudaFuncSetAttribute(mma_gemm<0, DIM>, cudaFuncAttributeMaxDynamicSharedMemorySize, GEMM_SMEM);
    cudaFuncSetAttribute(mma_gemm<1, DIM>, cudaFuncAttributeMaxDynamicSharedMemorySize, GEMM_SMEM);

    // 0) bf16 hi/lo conversions: x, w_qkv rows 1536..2304 (v weights), w_proj
    {
        int n4x = M_ROWS * DIM / 4;
        cvt_kernel<<<(n4x + 255) / 256, 256>>>(x, p_xh, p_xl, n4x);
        int n4w = DIM * DIM / 4;
        cvt_kernel<<<(n4w + 255) / 256, 256>>>(w_qkv + (size_t)2 * DIM * DIM, p_wvh, p_wvl, n4w);
        cvt_kernel<<<(n4w + 255) / 256, 256>>>(w_proj, p_wph, p_wpl, n4w);
    }
    // 1) V GEMM -> g_v
    {
        dim3 grid(DIM / 128, (M_ROWS + 127) / 128);
        mma_gemm<0, DIM><<<grid, 256, GEMM_SMEM>>>(p_xh, p_xl, p_wvh, p_wvl, nullptr, p_v);
    }
    // 2) prep (norm fused): vn hi + v hi/lo padded operands
    {
        int total = BHN * NKP;
        prep_kernel<<<(total + 255) / 256, 256>>>(p_v, p_vnh, p_vhh, p_vll);
    }
    // 3) row0: u vectors, batched scores, softmax+PV
    u_kernel<<<BHN, 256>>>(x, w_qkv, p_u);
    {
        dim3 grid(9, BATCH);
        score_kernel<<<grid, 256>>>(x, p_u, p_sc);
    }
    softpv_kernel<<<BHN, 256>>>(p_sc, p_v, p_oh, p_ol);
    // 4) VV cosine attention rows 1..1024 (1-pass S, cp.async pipelined)
    {
        dim3 grid(8, BHN);
        vv_mma_kernel<<<grid, 256, VV_SMEM>>>(p_vnh, p_vhh, p_vll, p_oh, p_ol);
    }
    // 5) proj GEMM + bias -> out
    {
        dim3 grid(DIM / 128, (M_ROWS + 127) / 128);
        mma_gemm<1, DIM><<<grid, 256, GEMM_SMEM>>>(p_oh, p_ol, p_wph, p_wpl, b_proj, out);
    }
}

// round 16
// speedup vs baseline: 1.4846x; 1.2066x over previous
#include <cuda_runtime.h>
#include <cuda_bf16.h>
#include <cuda_fp16.h>
#include <cstdint>

#define NH    12
#define HD    64
#define SEQ   1025
#define BATCH 8
#define DIM   768
#define M_ROWS (BATCH * SEQ)   /* 8200 */
#define BHN   (BATCH * NH)     /* 96 */
#define NKP   1152             /* keys padded to 9*128 */
#define SROW2 72               /* padded smem row (16-bit elems) for 64-dim tiles */
#define SROW  40               /* padded smem row (bf16) for 32-wide k-chunks */

// ---------------- scratch (device globals: allocation-free) ----------------
__device__ float g_v[(size_t)M_ROWS * DIM];    // v only (k,q eliminated algebraically)
__device__ float g_u[(size_t)BHN * DIM];       // row0 score vectors u = Wk^T q0
__device__ float g_sc[(size_t)BHN * SEQ];      // row0 raw scores

__device__ __nv_bfloat16 g_x_hi[(size_t)M_ROWS * DIM];
__device__ __nv_bfloat16 g_x_lo[(size_t)M_ROWS * DIM];
__device__ __nv_bfloat16 g_wv_hi[(size_t)DIM * DIM];
__device__ __nv_bfloat16 g_wv_lo[(size_t)DIM * DIM];
__device__ __nv_bfloat16 g_o_hi[(size_t)M_ROWS * DIM];
__device__ __nv_bfloat16 g_o_lo[(size_t)M_ROWS * DIM];
__device__ __nv_bfloat16 g_wp_hi[(size_t)DIM * DIM];
__device__ __nv_bfloat16 g_wp_lo[(size_t)DIM * DIM];

// VV attention operands (FP16): [bh][1152][64], zero padded past row 1024
__device__ __half g_vn_h[(size_t)BHN * NKP * HD];
__device__ __half g_v_h[(size_t)BHN * NKP * HD];

// ---------------- helpers ----------------
__device__ __forceinline__ float2 ffma2(float2 a, float2 b, float2 c) {
    float2 d;
    asm("fma.rn.f32x2 %0, %1, %2, %3;"
        : "=l"(*(unsigned long long*)&d)
        : "l"(*(unsigned long long*)&a),
          "l"(*(unsigned long long*)&b),
          "l"(*(unsigned long long*)&c));
    return d;
}

__device__ __forceinline__ uint32_t smem_u32(const void* p) {
    uint32_t a;
    asm("{ .reg .u64 t; cvta.to.shared.u64 t, %1; cvt.u32.u64 %0, t; }"
        : "=r"(a) : "l"(p));
    return a;
}

__device__ __forceinline__ void ldsm4(uint32_t* r, uint32_t addr) {
    asm volatile("ldmatrix.sync.aligned.m8n8.x4.shared.b16 {%0,%1,%2,%3}, [%4];"
                 : "=r"(r[0]), "=r"(r[1]), "=r"(r[2]), "=r"(r[3]) : "r"(addr));
}
__device__ __forceinline__ void ldsm4t(uint32_t* r, uint32_t addr) {
    asm volatile("ldmatrix.sync.aligned.m8n8.x4.trans.shared.b16 {%0,%1,%2,%3}, [%4];"
                 : "=r"(r[0]), "=r"(r[1]), "=r"(r[2]), "=r"(r[3]) : "r"(addr));
}

// bf16 mma (GEMMs)
__device__ __forceinline__ void mma16816(float* d, const uint32_t* a, const uint32_t* b) {
    asm volatile(
        "mma.sync.aligned.m16n8k16.row.col.f32.bf16.bf16.f32 "
        "{%0,%1,%2,%3}, {%4,%5,%6,%7}, {%8,%9}, {%0,%1,%2,%3};"
        : "+f"(d[0]), "+f"(d[1]), "+f"(d[2]), "+f"(d[3])
        : "r"(a[0]), "r"(a[1]), "r"(a[2]), "r"(a[3]), "r"(b[0]), "r"(b[1]));
}
// fp16 mma (VV attention)
__device__ __forceinline__ void mma16816h(float* d, const uint32_t* a, const uint32_t* b) {
    asm volatile(
        "mma.sync.aligned.m16n8k16.row.col.f32.f16.f16.f32 "
        "{%0,%1,%2,%3}, {%4,%5,%6,%7}, {%8,%9}, {%0,%1,%2,%3};"
        : "+f"(d[0]), "+f"(d[1]), "+f"(d[2]), "+f"(d[3])
        : "r"(a[0]), "r"(a[1]), "r"(a[2]), "r"(a[3]), "r"(b[0]), "r"(b[1]));
}

__device__ __forceinline__ uint32_t pack_bf16x2(float lo, float hi) {
    uint32_t r;
    asm("cvt.rn.bf16x2.f32 %0, %1, %2;" : "=r"(r) : "f"(hi), "f"(lo));
    return r;
}
__device__ __forceinline__ float2 unpack_bf16x2(uint32_t u) {
    __nv_bfloat162 b = *reinterpret_cast<__nv_bfloat162*>(&u);
    return make_float2(__bfloat162float(b.x), __bfloat162float(b.y));
}
__device__ __forceinline__ uint32_t pack_f16x2(float lo, float hi) {
    __half2 h = __floats2half2_rn(lo, hi);
    return *reinterpret_cast<uint32_t*>(&h);
}

// cp.async 16B with zero-fill when !ok
__device__ __forceinline__ void cp16(uint32_t dst, const void* src, bool ok) {
    asm volatile("cp.async.cg.shared.global [%0], [%1], 16, %2;"
                 :: "r"(dst), "l"(src), "r"(ok ? 16u : 0u));
}
#define CP_COMMIT() asm volatile("cp.async.commit_group;" ::: "memory")
#define CP_WAIT1()  asm volatile("cp.async.wait_group 1;" ::: "memory")
#define CP_WAIT0()  asm volatile("cp.async.wait_group 0;" ::: "memory")

// exp(0.125*s - 0.125) for s in [-1,1]: deg-4 Taylor on t in [-0.25, 0]
__device__ __forceinline__ float2 exp_poly2(float2 s) {
    float2 t = ffma2(s, make_float2(0.125f, 0.125f), make_float2(-0.125f, -0.125f));
    float2 hh = ffma2(t, make_float2(1.f/24.f, 1.f/24.f), make_float2(1.f/6.f, 1.f/6.f));
    hh = ffma2(t, hh, make_float2(0.5f, 0.5f));
    hh = ffma2(t, hh, make_float2(1.f, 1.f));
    hh = ffma2(t, hh, make_float2(1.f, 1.f));
    return hh;
}

__device__ __forceinline__ float warp_sum(float v) {
    v += __shfl_xor_sync(0xffffffffu, v, 16);
    v += __shfl_xor_sync(0xffffffffu, v, 8);
    v += __shfl_xor_sync(0xffffffffu, v, 4);
    v += __shfl_xor_sync(0xffffffffu, v, 2);
    v += __shfl_xor_sync(0xffffffffu, v, 1);
    return v;
}

// ============================================================================
// fp32 -> bf16 hi/lo split
// ============================================================================
__global__ void cvt_kernel(const float* __restrict__ in,
                           __nv_bfloat16* __restrict__ hi,
                           __nv_bfloat16* __restrict__ lo, int n4)
{
    int i = blockIdx.x * blockDim.x + threadIdx.x;
    if (i >= n4) return;
    float4 v = ((const float4*)in)[i];
    float vv[4] = {v.x, v.y, v.z, v.w};
    union { __nv_bfloat16 b[4]; uint2 u; } ph, pl;
#pragma unroll
    for (int j = 0; j < 4; j++) {
        __nv_bfloat16 h = __float2bfloat16(vv[j]);
        ph.b[j] = h;
        pl.b[j] = __float2bfloat16(vv[j] - __bfloat162float(h));
    }
    ((uint2*)hi)[i] = ph.u;
    ((uint2*)lo)[i] = pl.u;
}

// ============================================================================
// mma.sync bf16 hi/lo GEMM: 256 thr, 8 warps, 64x32 warp tiles, cp.async
// double buffer.  Block 128x128, BK=32.  D += Ah*Bh + Ah*Bl + Al*Bh.
// ============================================================================
#define STG 5120                    /* 128*SROW elems per buffer */
#define GEMM_SMEM (8 * STG * 2)     /* 2 stages x 4 arrays = 81920 bytes */

template<int MODE, int NOUT>
__global__ __launch_bounds__(256, 2) void mma_gemm(
    const __nv_bfloat16* __restrict__ Ahi, const __nv_bfloat16* __restrict__ Alo,
    const __nv_bfloat16* __restrict__ Bhi, const __nv_bfloat16* __restrict__ Blo,
    const float* __restrict__ bias, float* __restrict__ C)
{
    extern __shared__ __nv_bfloat16 smg[];
    const uint32_t smB = smem_u32(smg);

    const int tid = threadIdx.x;
    const int lane = tid & 31, wid = tid >> 5;
    const int warp_m = wid & 1;
    const int warp_n = wid >> 1;
    const int bm = blockIdx.y * 128, bn = blockIdx.x * 128;

    const int lr = tid >> 1, lk = (tid & 1) * 16;
    const int am = bm + lr;
    const bool aok = (am < M_ROWS);
    int arow;
    if (MODE == 0) arow = (am % SEQ) * BATCH + (am / SEQ);
    else           arow = am;
    if (!aok) arow = 0;
    const size_t aoff = (size_t)arow * DIM + lk;
    const size_t boff = (size_t)(bn + lr) * DIM + lk;
    const uint32_t rowb = (uint32_t)(lr * SROW + lk) * 2;

    const int a_r = warp_m * 64 + (lane & 7) + ((lane >> 3) & 1) * 8;
    const int a_k = (lane >> 4) * 8;
    const uint32_t aoffb = (uint32_t)(a_r * SROW + a_k) * 2;
    const int b_n = warp_n * 32 + (lane & 7) + (lane >> 4) * 8;
    const int b_k = ((lane >> 3) & 1) * 8;
    const uint32_t boffb = (uint32_t)(b_n * SROW + b_k) * 2;

    float acc[4][4][4];
#pragma unroll
    for (int i = 0; i < 4; i++)
#pragma unroll
        for (int j = 0; j < 4; j++)
#pragma unroll
            for (int r = 0; r < 4; r++) acc[i][j][r] = 0.f;

#define LOAD_STAGE(ST, GK)                                                    \
    do {                                                                      \
        const uint32_t s0 = smB + (uint32_t)((ST) * 4) * (STG * 2) + rowb;    \
        cp16(s0 + 0 * (STG * 2),      Ahi + aoff + (GK),     aok);            \
        cp16(s0 + 0 * (STG * 2) + 16, Ahi + aoff + (GK) + 8, aok);            \
        cp16(s0 + 1 * (STG * 2),      Alo + aoff + (GK),     aok);            \
        cp16(s0 + 1 * (STG * 2) + 16, Alo + aoff + (GK) + 8, aok);            \
        cp16(s0 + 2 * (STG * 2),      Bhi + boff + (GK),     true);           \
        cp16(s0 + 2 * (STG * 2) + 16, Bhi + boff + (GK) + 8, true);           \
        cp16(s0 + 3 * (STG * 2),      Blo + boff + (GK),     true);           \
        cp16(s0 + 3 * (STG * 2) + 16, Blo + boff + (GK) + 8, true);           \
        CP_COMMIT();                                                          \
    } while (0)

    LOAD_STAGE(0, 0);

#pragma unroll 1
    for (int kc = 0; kc < DIM / 32; kc++) {
        const int st = kc & 1;
        if (kc < DIM / 32 - 1) {
            LOAD_STAGE(st ^ 1, (size_t)(kc + 1) * 32);
            CP_WAIT1();
        } else {
            CP_WAIT0();
        }
        __syncthreads();

        const uint32_t aAh = smB + (uint32_t)(st * 4 + 0) * (STG * 2) + aoffb;
        const uint32_t aAl = smB + (uint32_t)(st * 4 + 1) * (STG * 2) + aoffb;
        const uint32_t aBh = smB + (uint32_t)(st * 4 + 2) * (STG * 2) + boffb;
        const uint32_t aBl = smB + (uint32_t)(st * 4 + 3) * (STG * 2) + boffb;

#pragma unroll
        for (int kh = 0; kh < 2; kh++) {
            const uint32_t kb = kh * 32;
            uint32_t ah[4][4], al[4][4];
#pragma unroll
            for (int mi = 0; mi < 4; mi++) {
                ldsm4(ah[mi], aAh + mi * (16 * SROW * 2) + kb);
                ldsm4(al[mi], aAl + mi * (16 * SROW * 2) + kb);
            }
#pragma unroll
            for (int np = 0; np < 2; np++) {
                uint32_t bh2[4], bl2[4];
                ldsm4(bh2, aBh + np * (16 * SROW * 2) + kb);
                ldsm4(bl2, aBl + np * (16 * SROW * 2) + kb);
#pragma unroll
                for (int mi = 0; mi < 4; mi++) {
                    mma16816(acc[mi][2 * np],     ah[mi], bh2);
                    mma16816(acc[mi][2 * np],     ah[mi], bl2);
                    mma16816(acc[mi][2 * np],     al[mi], bh2);
                    mma16816(acc[mi][2 * np + 1], ah[mi], bh2 + 2);
                    mma16816(acc[mi][2 * np + 1], ah[mi], bl2 + 2);
                    mma16816(acc[mi][2 * np + 1], al[mi], bh2 + 2);
                }
            }
        }
        __syncthreads();
    }

    const int col0 = bn + warp_n * 32 + (lane & 3) * 2;
    const int row0 = bm + warp_m * 64 + (lane >> 2);
#pragma unroll
    for (int mi = 0; mi < 4; mi++) {
#pragma unroll
        for (int half = 0; half < 2; half++) {
            const int m = row0 + mi * 16 + half * 8;
            if (m >= M_ROWS) continue;
            size_t crow;
            if (MODE == 0) crow = (size_t)m * NOUT;
            else           crow = (size_t)((m % SEQ) * BATCH + (m / SEQ)) * NOUT;
#pragma unroll
            for (int nj = 0; nj < 4; nj++) {
                const int col = col0 + nj * 8;
                float2 o = make_float2(acc[mi][nj][2 * half], acc[mi][nj][2 * half + 1]);
                if (MODE == 1) {
                    float2 bv = *(const float2*)&bias[col];
                    o.x += bv.x; o.y += bv.y;
                }
                *(float2*)&C[crow + col] = o;
            }
        }
    }
}

// ============================================================================
// prep (norm fused): per (bh,row) write FP16 of vn = v*inv and of raw v;
// zero-pad rows >= SEQ.
// ============================================================================
__global__ void prep_kernel(const float* __restrict__ v,
                            __half* __restrict__ vnh, __half* __restrict__ vh_)
{
    int idx = blockIdx.x * blockDim.x + threadIdx.x;
    if (idx >= BHN * NKP) return;
    const int bh = idx / NKP, row = idx % NKP;
    const int b = bh / NH, h = bh % NH;
    const size_t dst = (size_t)idx * HD;
    if (row < SEQ) {
        const float* src = v + (size_t)(b * SEQ + row) * DIM + h * HD;
        float4 vbuf[16];
        float acc = 0.f;
#pragma unroll
        for (int c = 0; c < 16; c++) {
            float4 t = *(const float4*)(src + 4 * c);
            vbuf[c] = t;
            acc += t.x * t.x + t.y * t.y + t.z * t.z + t.w * t.w;
        }
        const float iv = 1.f / fmaxf(sqrtf(acc), 1e-6f);
#pragma unroll 4
        for (int c = 0; c < 16; c++) {
            float vv[4] = {vbuf[c].x, vbuf[c].y, vbuf[c].z, vbuf[c].w};
            union { __half b[4]; uint2 u; } nh, rh;
#pragma unroll
            for (int j = 0; j < 4; j++) {
                nh.b[j] = __float2half_rn(vv[j] * iv);
                rh.b[j] = __float2half_rn(vv[j]);
            }
            *(uint2*)(vnh + dst + 4 * c) = nh.u;
            *(uint2*)(vh_ + dst + 4 * c) = rh.u;
        }
    } else {
        uint2 z = {0, 0};
#pragma unroll 4
        for (int c = 0; c < HD; c += 4) {
            *(uint2*)(vnh + dst + c) = z;
            *(uint2*)(vh_ + dst + c) = z;
        }
    }
}

// ============================================================================
// row0 stage A: per (b,h) u = Wk^T (0.125 * Wq x0), exact fp32. 96 blocks.
// ============================================================================
__global__ __launch_bounds__(256) void u_kernel(const float* __restrict__ x,
                                                const float* __restrict__ w_qkv,
                                                float* __restrict__ u_out)
{
    __shared__ float q0s[HD];
    const int tid = threadIdx.x;
    const int lane = tid & 31, wid = tid >> 5;
    const int b = blockIdx.x / NH, h = blockIdx.x % NH;

    {
        const float4* xr4 = (const float4*)(x + (size_t)b * DIM);
#pragma unroll 1
        for (int i = 0; i < 8; i++) {
            const int d = wid * 8 + i;
            const float4* wrow = (const float4*)(w_qkv + (size_t)(h * HD + d) * DIM);
            float acc = 0.f;
#pragma unroll
            for (int c = lane; c < DIM / 4; c += 32) {
                float4 wv = wrow[c];
                float4 xv = xr4[c];
                acc += wv.x * xv.x + wv.y * xv.y + wv.z * xv.z + wv.w * xv.w;
            }
            acc = warp_sum(acc);
            if (lane == 0) q0s[d] = 0.125f * acc;
        }
    }
    __syncthreads();

    const float* wk = w_qkv + ((size_t)DIM + h * HD) * DIM;
    float* uo = u_out + (size_t)blockIdx.x * DIM;
    for (int k = tid; k < DIM; k += 256) {
        float acc = 0.f;
#pragma unroll 8
        for (int dd = 0; dd < HD; dd++)
            acc += q0s[dd] * wk[(size_t)dd * DIM + k];
        uo[k] = acc;
    }
}

// ============================================================================
// row0 stage B: scores for all 12 heads at once; x read once per batch-tile.
// ============================================================================
__global__ __launch_bounds__(256) void score_kernel(const float* __restrict__ x,
                                                    const float* __restrict__ u_in,
                                                    float* __restrict__ sc_out)
{
    __shared__ float sU[NH * DIM];   // 36 KB
    const int tid = threadIdx.x;
    const int lane = tid & 31, wid = tid >> 5;
    const int tile = blockIdx.x, b = blockIdx.y;

    for (int i = tid; i < NH * DIM; i += 256)
        sU[i] = u_in[(size_t)b * NH * DIM + i];
    __syncthreads();

    const int j0 = tile * 128 + wid * 16;
#pragma unroll 1
    for (int r = 0; r < 16; r++) {
        const int j = j0 + r;
        if (j >= SEQ) break;
        const float4* xr = (const float4*)(x + (size_t)(j * BATCH + b) * DIM);
        float acc[NH];
#pragma unroll
        for (int h = 0; h < NH; h++) acc[h] = 0.f;
#pragma unroll 1
        for (int c = lane; c < DIM / 4; c += 32) {
            float4 xv = xr[c];
#pragma unroll
            for (int h = 0; h < NH; h++) {
                float4 uv = ((const float4*)(sU + h * DIM))[c];
                acc[h] += uv.x * xv.x + uv.y * xv.y + uv.z * xv.z + uv.w * xv.w;
            }
        }
#pragma unroll
        for (int h = 0; h < NH; h++) acc[h] = warp_sum(acc[h]);
        if (lane == 0) {
#pragma unroll
            for (int h = 0; h < NH; h++)
                sc_out[(size_t)(b * NH + h) * SEQ + j] = acc[h];
        }
    }
}

// ============================================================================
// row0 stage C: per (b,h) softmax + PV from g_v; writes bf16 hi/lo output.
// ============================================================================
__global__ __launch_bounds__(256) void softpv_kernel(const float* __restrict__ sc_in,
                                                     const float* __restrict__ v,
                                                     __nv_bfloat16* __restrict__ ohi,
                                                     __nv_bfloat16* __restrict__ olo)
{
    __shared__ float sc[SEQ];
    __shared__ float red[256];
    __shared__ float part[4][HD];
    const int tid = threadIdx.x;
    const int b = blockIdx.x / NH, h = blockIdx.x % NH;

    for (int j = tid; j < SEQ; j += 256)
        sc[j] = sc_in[(size_t)blockIdx.x * SEQ + j];
    __syncthreads();

    float lmax = -1e30f;
    for (int j = tid; j < SEQ; j += 256) lmax = fmaxf(lmax, sc[j]);
    red[tid] = lmax; __syncthreads();
    for (int s = 128; s > 0; s >>= 1) {
        if (tid < s) red[tid] = fmaxf(red[tid], red[tid + s]);
        __syncthreads();
    }
    float mval = red[0];
    __syncthreads();

    float lsum = 0.f;
    for (int j = tid; j < SEQ; j += 256) {
        float p = __expf(sc[j] - mval);
        sc[j] = p;
        lsum += p;
    }
    red[tid] = lsum; __syncthreads();
    for (int s = 128; s > 0; s >>= 1) {
        if (tid < s) red[tid] += red[tid + s];
        __syncthreads();
    }
    float l = red[0];
    __syncthreads();

    const int d = tid & 63, pi = tid >> 6;
    float acc = 0.f;
    const float* vbase = v + (size_t)(b * SEQ) * DIM + h * HD;
    for (int j = pi; j < SEQ; j += 4)
        acc += sc[j] * vbase[(size_t)j * DIM + d];
    part[pi][d] = acc;
    __syncthreads();
    if (tid < HD) {
        float s = (part[0][tid] + part[1][tid] + part[2][tid] + part[3][tid]) / l;
        const size_t o = (size_t)(b * SEQ) * DIM + h * HD + tid;
        __nv_bfloat16 hh = __float2bfloat16(s);
        ohi[o] = hh;
        olo[o] = __float2bfloat16(s - __bfloat162float(hh));
    }
}

// ============================================================================
// Fused FA2-style VV attention (FP16), rows 1..1024, cp.async double-buffered.
// S = Q·K (1-pass fp16); PV = P·V (1-pass fp16) — fp16's 11-bit mantissa
// gives ~3e-4 output error, 3x under threshold.
// ============================================================================
#define VVT (2 * 128 * SROW2)             /* fp16 elems per stage (K,V) */
#define VV_SMEM (2 * VVT * 2)             /* 73728 bytes */

__global__ __launch_bounds__(256, 1)
void vv_mma_kernel(const __half* __restrict__ vnh, const __half* __restrict__ vvh,
                   __nv_bfloat16* __restrict__ ohi, __nv_bfloat16* __restrict__ olo)
{
    extern __shared__ __half smh[];
    const uint32_t smB = smem_u32(smh);

    const int tid = threadIdx.x, lane = tid & 31, wid = tid >> 5;
    const int bh = blockIdx.y, qt = blockIdx.x;
    const int b = bh / NH, h = bh % NH;
    const int q0 = 1 + qt * 128;
    const size_t base = (size_t)bh * NKP * HD;

    const int ld_r = tid >> 1, ld_c = (tid & 1) * 32;
    const uint32_t ld_sm = (uint32_t)(ld_r * SROW2 + ld_c) * 2;
    const size_t   ld_g0 = (size_t)ld_r * HD + ld_c;

#define SK(s)  (smB + (uint32_t)(s) * (VVT * 2))
#define SVH(s) (SK(s) + 128 * SROW2 * 2)

#define VV_ISSUE(s, kt)                                                        \
    do {                                                                       \
        const size_t g = base + (size_t)(kt) * 128 * HD + ld_g0;               \
        const uint32_t dK = SK(s) + ld_sm, dH = SVH(s) + ld_sm;                \
        cp16(dK + 0,  vnh + g,      true); cp16(dK + 16, vnh + g + 8,  true);  \
        cp16(dK + 32, vnh + g + 16, true); cp16(dK + 48, vnh + g + 24, true);  \
        cp16(dH + 0,  vvh + g,      true); cp16(dH + 16, vvh + g + 8,  true);  \
        cp16(dH + 32, vvh + g + 16, true); cp16(dH + 48, vvh + g + 24, true);  \
        CP_COMMIT();                                                           \
    } while (0)

    // prologue: start tile 0 into stage 0 immediately
    VV_ISSUE(0, 0);

    // stage Q into stage-1 K buffer via regular loads; extract fragments
    {
        const size_t g = base + (size_t)(q0 + ld_r) * HD + ld_c;
        uint4* dh = (uint4*)((char*)smh + (VVT * 2) + (ld_r * SROW2 + ld_c) * 2);
        const uint4* p1 = (const uint4*)(vnh + g);
#pragma unroll
        for (int i = 0; i < 4; i++) dh[i] = p1[i];
    }
    __syncthreads();
    uint32_t qh[4][4];
    {
        const int a_r = wid * 16 + (lane & 7) + ((lane >> 3) & 1) * 8;
        const int a_k = (lane >> 4) * 8;
        const uint32_t ah = SK(1) + (uint32_t)(a_r * SROW2 + a_k) * 2;
#pragma unroll
        for (int kt = 0; kt < 4; kt++)
            ldsm4(qh[kt], ah + kt * 16 * 2);
    }

    float oacc[8][4];
#pragma unroll
    for (int g = 0; g < 8; g++)
#pragma unroll
        for (int r = 0; r < 4; r++) oacc[g][r] = 0.f;
    float la = 0.f, lb = 0.f;

    const int b_n = (lane & 7) + (lane >> 4) * 8;
    const int b_k = ((lane >> 3) & 1) * 8;
    const int t_r = lane & 15, t_c = (lane >> 4) * 8;

#pragma unroll 1
    for (int ktile = 0; ktile < 9; ktile++) {
        const int st = ktile & 1;
        CP_WAIT0();
        __syncthreads();
        if (ktile < 8) VV_ISSUE(st ^ 1, ktile + 1);

        const uint32_t sKh_u = SK(st), sVh_u = SVH(st);

        // scores: 1-pass fp16 Q x K
        float p[16][4];
#pragma unroll
        for (int f = 0; f < 16; f++)
#pragma unroll
            for (int r = 0; r < 4; r++) p[f][r] = 0.f;

#pragma unroll
        for (int kt = 0; kt < 4; kt++) {
#pragma unroll
            for (int g = 0; g < 8; g++) {
                uint32_t kh_[4];
                const uint32_t off = (uint32_t)((g * 16 + b_n) * SROW2 + kt * 16 + b_k) * 2;
                ldsm4(kh_, sKh_u + off);
                mma16816h(p[2*g],   qh[kt], kh_);
                mma16816h(p[2*g+1], qh[kt], kh_ + 2);
            }
        }

        // softmax probs (fixed max), accumulate l (fp32)
#pragma unroll
        for (int f = 0; f < 16; f++) {
            float2 e0 = exp_poly2(make_float2(p[f][0], p[f][1]));
            float2 e1 = exp_poly2(make_float2(p[f][2], p[f][3]));
            p[f][0] = e0.x; p[f][1] = e0.y; p[f][2] = e1.x; p[f][3] = e1.y;
            la += e0.x + e0.y;
            lb += e1.x + e1.y;
        }

        // PV: 1-pass fp16 P x V
#pragma unroll
        for (int kt = 0; kt < 8; kt++) {
            uint32_t pah[4];
            {
                const float* sA = p[2 * kt];
                const float* sB = p[2 * kt + 1];
                pah[0] = pack_f16x2(sA[0], sA[1]);
                pah[1] = pack_f16x2(sA[2], sA[3]);
                pah[2] = pack_f16x2(sB[0], sB[1]);
                pah[3] = pack_f16x2(sB[2], sB[3]);
            }
#pragma unroll
            for (int g = 0; g < 4; g++) {
                uint32_t vh_[4];
                const uint32_t off = (uint32_t)((kt * 16 + t_r) * SROW2 + g * 16 + t_c) * 2;
                ldsm4t(vh_, sVh_u + off);
                mma16816h(oacc[2*g],   pah, vh_);
                mma16816h(oacc[2*g+1], pah, vh_ + 2);
            }
        }
    }

    // l reduce + pad correction + hi/lo output
    la += __shfl_xor_sync(0xffffffffu, la, 1);
    la += __shfl_xor_sync(0xffffffffu, la, 2);
    lb += __shfl_xor_sync(0xffffffffu, lb, 1);
    lb += __shfl_xor_sync(0xffffffffu, lb, 2);
    float P0;
    {
        float t = -0.125f;
        float hh = fmaf(t, 1.f/24.f, 1.f/6.f);
        hh = fmaf(t, hh, 0.5f);
        hh = fmaf(t, hh, 1.f);
        hh = fmaf(t, hh, 1.f);
        P0 = hh;
    }
    la -= 127.f * P0;
    lb -= 127.f * P0;
    const float ia = 1.f / la, ib = 1.f / lb;

    const int row_a = q0 + wid * 16 + (lane >> 2);
    const int col0 = h * HD + (lane & 3) * 2;
    const size_t oa = (size_t)(b * SEQ + row_a) * DIM;
    const size_t ob = (size_t)(b * SEQ + row_a + 8) * DIM;
#pragma unroll
    for (int g = 0; g < 8; g++) {
        float x0 = oacc[g][0] * ia, x1 = oacc[g][1] * ia;
        float y0 = oacc[g][2] * ib, y1 = oacc[g][3] * ib;
        uint32_t xh = pack_bf16x2(x0, x1);
        uint32_t yh = pack_bf16x2(y0, y1);
        float2 fxh = unpack_bf16x2(xh);
        float2 fyh = unpack_bf16x2(yh);
        uint32_t xl = pack_bf16x2(x0 - fxh.x, x1 - fxh.y);
        uint32_t yl = pack_bf16x2(y0 - fyh.x, y1 - fyh.y);
        *(uint32_t*)(ohi + oa + col0 + g * 8) = xh;
        *(uint32_t*)(olo + oa + col0 + g * 8) = xl;
        *(uint32_t*)(ohi + ob + col0 + g * 8) = yh;
        *(uint32_t*)(olo + ob + col0 + g * 8) = yl;
    }
}

// ============================================================================
extern "C" void kernel_launch(void* const* d_in, const int* in_sizes, int n_in,
                              void* d_out, int out_size)
{
    const float* x      = (const float*)d_in[0];
    const float* w_qkv  = (const float*)d_in[1];
    const float* w_proj = (const float*)d_in[2];
    const float* b_proj = (const float*)d_in[3];
    float* out = (float*)d_out;

    float *p_v, *p_u, *p_sc;
    cudaGetSymbolAddress((void**)&p_v,  g_v);
    cudaGetSymbolAddress((void**)&p_u,  g_u);
    cudaGetSymbolAddress((void**)&p_sc, g_sc);
    __nv_bfloat16 *p_xh, *p_xl, *p_wvh, *p_wvl, *p_oh, *p_ol, *p_wph, *p_wpl;
    __half *p_vnh, *p_vhh;
    cudaGetSymbolAddress((void**)&p_xh,  g_x_hi);
    cudaGetSymbolAddress((void**)&p_xl,  g_x_lo);
    cudaGetSymbolAddress((void**)&p_wvh, g_wv_hi);
    cudaGetSymbolAddress((void**)&p_wvl, g_wv_lo);
    cudaGetSymbolAddress((void**)&p_oh,  g_o_hi);
    cudaGetSymbolAddress((void**)&p_ol,  g_o_lo);
    cudaGetSymbolAddress((void**)&p_wph, g_wp_hi);
    cudaGetSymbolAddress((void**)&p_wpl, g_wp_lo);
    cudaGetSymbolAddress((void**)&p_vnh, g_vn_h);
    cudaGetSymbolAddress((void**)&p_vhh, g_v_h);

    cudaFuncSetAttribute(vv_mma_kernel, cudaFuncAttributeMaxDynamicSharedMemorySize, VV_SMEM);
    cudaFuncSetAttribute(mma_gemm<0, DIM>, cudaFuncAttributeMaxDynamicSharedMemorySize, GEMM_SMEM);
    cudaFuncSetAttribute(mma_gemm<1, DIM>, cudaFuncAttributeMaxDynamicSharedMemorySize, GEMM_SMEM);

    // 0) bf16 hi/lo conversions: x, w_qkv rows 1536..2304 (v weights), w_proj
    {
        int n4x = M_ROWS * DIM / 4;
        cvt_kernel<<<(n4x + 255) / 256, 256>>>(x, p_xh, p_xl, n4x);
        int n4w = DIM * DIM / 4;
        cvt_kernel<<<(n4w + 255) / 256, 256>>>(w_qkv + (size_t)2 * DIM * DIM, p_wvh, p_wvl, n4w);
        cvt_kernel<<<(n4w + 255) / 256, 256>>>(w_proj, p_wph, p_wpl, n4w);
    }
    // 1) V GEMM -> g_v
    {
        dim3 grid(DIM / 128, (M_ROWS + 127) / 128);
        mma_gemm<0, DIM><<<grid, 256, GEMM_SMEM>>>(p_xh, p_xl, p_wvh, p_wvl, nullptr, p_v);
    }
    // 2) prep (norm fused): vn/v fp16 padded operands
    {
        int total = BHN * NKP;
        prep_kernel<<<(total + 255) / 256, 256>>>(p_v, p_vnh, p_vhh);
    }
    // 3) row0: u vectors, batched scores, softmax+PV
    u_kernel<<<BHN, 256>>>(x, w_qkv, p_u);
    {
        dim3 grid(9, BATCH);
        score_kernel<<<grid, 256>>>(x, p_u, p_sc);
    }
    softpv_kernel<<<BHN, 256>>>(p_sc, p_v, p_oh, p_ol);
    // 4) VV cosine attention rows 1..1024 (fp16, 1-pass S, 1-pass PV)
    {
        dim3 grid(8, BHN);
        vv_mma_kernel<<<grid, 256, VV_SMEM>>>(p_vnh, p_vhh, p_oh, p_ol);
    }
    // 5) proj GEMM + bias -> out
    {
        dim3 grid(DIM / 128, (M_ROWS + 127) / 128);
        mma_gemm<1, DIM><<<grid, 256, GEMM_SMEM>>>(p_oh, p_ol, p_wph, p_wpl, b_proj, out);
    }
}

// round 17
// speedup vs baseline: 1.6862x; 1.1358x over previous
#include <cuda_runtime.h>
#include <cuda_bf16.h>
#include <cuda_fp16.h>
#include <cstdint>

#define NH    12
#define HD    64
#define SEQ   1025
#define BATCH 8
#define DIM   768
#define M_ROWS (BATCH * SEQ)   /* 8200 */
#define BHN   (BATCH * NH)     /* 96 */
#define NKP   1152             /* keys padded to 9*128 */
#define SROW2 72               /* padded smem row (16-bit elems) for 64-dim tiles */
#define SROW  40               /* padded smem row for 32-wide k-chunks */

// ---------------- scratch (device globals: allocation-free) ----------------
__device__ float g_v[(size_t)M_ROWS * DIM];    // v (fp32, feeds prep + row0 PV)
__device__ float g_u[(size_t)BHN * DIM];       // row0 score vectors u = Wk^T q0
__device__ float g_sc[(size_t)BHN * SEQ];      // row0 raw scores

__device__ __half g_xh[(size_t)M_ROWS * DIM];  // x fp16 hi
__device__ __half g_xl[(size_t)M_ROWS * DIM];  // x fp16 lo
__device__ __half g_wv[(size_t)DIM * DIM];     // v weights fp16
__device__ __half g_oh[(size_t)M_ROWS * DIM];  // attention out fp16 hi
__device__ __half g_ol[(size_t)M_ROWS * DIM];  // attention out fp16 lo
__device__ __half g_wp[(size_t)DIM * DIM];     // proj weights fp16

// VV attention operands (FP16): [bh][1152][64], zero padded past row 1024
__device__ __half g_vn_h[(size_t)BHN * NKP * HD];
__device__ __half g_v_h[(size_t)BHN * NKP * HD];

// ---------------- helpers ----------------
__device__ __forceinline__ float2 ffma2(float2 a, float2 b, float2 c) {
    float2 d;
    asm("fma.rn.f32x2 %0, %1, %2, %3;"
        : "=l"(*(unsigned long long*)&d)
        : "l"(*(unsigned long long*)&a),
          "l"(*(unsigned long long*)&b),
          "l"(*(unsigned long long*)&c));
    return d;
}

__device__ __forceinline__ uint32_t smem_u32(const void* p) {
    uint32_t a;
    asm("{ .reg .u64 t; cvta.to.shared.u64 t, %1; cvt.u32.u64 %0, t; }"
        : "=r"(a) : "l"(p));
    return a;
}

__device__ __forceinline__ void ldsm4(uint32_t* r, uint32_t addr) {
    asm volatile("ldmatrix.sync.aligned.m8n8.x4.shared.b16 {%0,%1,%2,%3}, [%4];"
                 : "=r"(r[0]), "=r"(r[1]), "=r"(r[2]), "=r"(r[3]) : "r"(addr));
}
__device__ __forceinline__ void ldsm4t(uint32_t* r, uint32_t addr) {
    asm volatile("ldmatrix.sync.aligned.m8n8.x4.trans.shared.b16 {%0,%1,%2,%3}, [%4];"
                 : "=r"(r[0]), "=r"(r[1]), "=r"(r[2]), "=r"(r[3]) : "r"(addr));
}

// fp16 mma
__device__ __forceinline__ void mma16816h(float* d, const uint32_t* a, const uint32_t* b) {
    asm volatile(
        "mma.sync.aligned.m16n8k16.row.col.f32.f16.f16.f32 "
        "{%0,%1,%2,%3}, {%4,%5,%6,%7}, {%8,%9}, {%0,%1,%2,%3};"
        : "+f"(d[0]), "+f"(d[1]), "+f"(d[2]), "+f"(d[3])
        : "r"(a[0]), "r"(a[1]), "r"(a[2]), "r"(a[3]), "r"(b[0]), "r"(b[1]));
}

__device__ __forceinline__ uint32_t pack_f16x2(float lo, float hi) {
    __half2 h = __floats2half2_rn(lo, hi);
    return *reinterpret_cast<uint32_t*>(&h);
}
__device__ __forceinline__ float2 unpack_f16x2(uint32_t u) {
    __half2 h = *reinterpret_cast<__half2*>(&u);
    return make_float2(__half2float(h.x), __half2float(h.y));
}

// cp.async 16B with zero-fill when !ok
__device__ __forceinline__ void cp16(uint32_t dst, const void* src, bool ok) {
    asm volatile("cp.async.cg.shared.global [%0], [%1], 16, %2;"
                 :: "r"(dst), "l"(src), "r"(ok ? 16u : 0u));
}
#define CP_COMMIT() asm volatile("cp.async.commit_group;" ::: "memory")
#define CP_WAIT1()  asm volatile("cp.async.wait_group 1;" ::: "memory")
#define CP_WAIT0()  asm volatile("cp.async.wait_group 0;" ::: "memory")

// exp(0.125*s - 0.125) for s in [-1,1]: deg-4 Taylor on t in [-0.25, 0]
__device__ __forceinline__ float2 exp_poly2(float2 s) {
    float2 t = ffma2(s, make_float2(0.125f, 0.125f), make_float2(-0.125f, -0.125f));
    float2 hh = ffma2(t, make_float2(1.f/24.f, 1.f/24.f), make_float2(1.f/6.f, 1.f/6.f));
    hh = ffma2(t, hh, make_float2(0.5f, 0.5f));
    hh = ffma2(t, hh, make_float2(1.f, 1.f));
    hh = ffma2(t, hh, make_float2(1.f, 1.f));
    return hh;
}

__device__ __forceinline__ float warp_sum(float v) {
    v += __shfl_xor_sync(0xffffffffu, v, 16);
    v += __shfl_xor_sync(0xffffffffu, v, 8);
    v += __shfl_xor_sync(0xffffffffu, v, 4);
    v += __shfl_xor_sync(0xffffffffu, v, 2);
    v += __shfl_xor_sync(0xffffffffu, v, 1);
    return v;
}

// ============================================================================
// fp32 -> fp16 hi/lo split (for activations)
// ============================================================================
__global__ void cvt_hl_kernel(const float* __restrict__ in,
                              __half* __restrict__ hi, __half* __restrict__ lo, int n4)
{
    int i = blockIdx.x * blockDim.x + threadIdx.x;
    if (i >= n4) return;
    float4 v = ((const float4*)in)[i];
    float vv[4] = {v.x, v.y, v.z, v.w};
    union { __half b[4]; uint2 u; } ph, pl;
#pragma unroll
    for (int j = 0; j < 4; j++) {
        __half h = __float2half_rn(vv[j]);
        ph.b[j] = h;
        pl.b[j] = __float2half_rn(vv[j] - __half2float(h));
    }
    ((uint2*)hi)[i] = ph.u;
    ((uint2*)lo)[i] = pl.u;
}

// fp32 -> fp16 (weights)
__global__ void cvt_h_kernel(const float* __restrict__ in,
                             __half* __restrict__ hi, int n4)
{
    int i = blockIdx.x * blockDim.x + threadIdx.x;
    if (i >= n4) return;
    float4 v = ((const float4*)in)[i];
    union { __half b[4]; uint2 u; } ph;
    ph.b[0] = __float2half_rn(v.x);
    ph.b[1] = __float2half_rn(v.y);
    ph.b[2] = __float2half_rn(v.z);
    ph.b[3] = __float2half_rn(v.w);
    ((uint2*)hi)[i] = ph.u;
}

// ============================================================================
// fp16 2-pass GEMM: C[m][j] = sum_k A[m][k]*W[j][k] (+bias), K=768.
// D += Ah*Bh + Al*Bh (A fp16 hi/lo, B fp16; error = weight rounding ~1.7e-4).
// 256 thr, 8 warps, 64x32 warp tiles, cp.async double buffer, BK=32.
// MODE 0 (v):    A row m -> x row (m%SEQ)*B + m/SEQ,  C -> g_v[m][j]
// MODE 1 (proj): A row m -> o row m, C -> out[(m%SEQ)*B + m/SEQ][j] + bias
// ============================================================================
#define STG 5120                    /* 128*SROW elems per buffer */
#define GEMM_SMEM (6 * STG * 2)     /* 2 stages x 3 arrays = 61440 bytes */

template<int MODE, int NOUT>
__global__ __launch_bounds__(256, 2) void mma_gemm(
    const __half* __restrict__ Ahi, const __half* __restrict__ Alo,
    const __half* __restrict__ Bhi,
    const float* __restrict__ bias, float* __restrict__ C)
{
    extern __shared__ __half smg[];
    const uint32_t smB = smem_u32(smg);

    const int tid = threadIdx.x;
    const int lane = tid & 31, wid = tid >> 5;
    const int warp_m = wid & 1;
    const int warp_n = wid >> 1;
    const int bm = blockIdx.y * 128, bn = blockIdx.x * 128;

    const int lr = tid >> 1, lk = (tid & 1) * 16;
    const int am = bm + lr;
    const bool aok = (am < M_ROWS);
    int arow;
    if (MODE == 0) arow = (am % SEQ) * BATCH + (am / SEQ);
    else           arow = am;
    if (!aok) arow = 0;
    const size_t aoff = (size_t)arow * DIM + lk;
    const size_t boff = (size_t)(bn + lr) * DIM + lk;
    const uint32_t rowb = (uint32_t)(lr * SROW + lk) * 2;

    const int a_r = warp_m * 64 + (lane & 7) + ((lane >> 3) & 1) * 8;
    const int a_k = (lane >> 4) * 8;
    const uint32_t aoffb = (uint32_t)(a_r * SROW + a_k) * 2;
    const int b_n = warp_n * 32 + (lane & 7) + (lane >> 4) * 8;
    const int b_k = ((lane >> 3) & 1) * 8;
    const uint32_t boffb = (uint32_t)(b_n * SROW + b_k) * 2;

    float acc[4][4][4];
#pragma unroll
    for (int i = 0; i < 4; i++)
#pragma unroll
        for (int j = 0; j < 4; j++)
#pragma unroll
            for (int r = 0; r < 4; r++) acc[i][j][r] = 0.f;

#define LOAD_STAGE(ST, GK)                                                    \
    do {                                                                      \
        const uint32_t s0 = smB + (uint32_t)((ST) * 3) * (STG * 2) + rowb;    \
        cp16(s0 + 0 * (STG * 2),      Ahi + aoff + (GK),     aok);            \
        cp16(s0 + 0 * (STG * 2) + 16, Ahi + aoff + (GK) + 8, aok);            \
        cp16(s0 + 1 * (STG * 2),      Alo + aoff + (GK),     aok);            \
        cp16(s0 + 1 * (STG * 2) + 16, Alo + aoff + (GK) + 8, aok);            \
        cp16(s0 + 2 * (STG * 2),      Bhi + boff + (GK),     true);           \
        cp16(s0 + 2 * (STG * 2) + 16, Bhi + boff + (GK) + 8, true);           \
        CP_COMMIT();                                                          \
    } while (0)

    LOAD_STAGE(0, 0);

#pragma unroll 1
    for (int kc = 0; kc < DIM / 32; kc++) {
        const int st = kc & 1;
        if (kc < DIM / 32 - 1) {
            LOAD_STAGE(st ^ 1, (size_t)(kc + 1) * 32);
            CP_WAIT1();
        } else {
            CP_WAIT0();
        }
        __syncthreads();

        const uint32_t aAh = smB + (uint32_t)(st * 3 + 0) * (STG * 2) + aoffb;
        const uint32_t aAl = smB + (uint32_t)(st * 3 + 1) * (STG * 2) + aoffb;
        const uint32_t aBh = smB + (uint32_t)(st * 3 + 2) * (STG * 2) + boffb;

#pragma unroll
        for (int kh = 0; kh < 2; kh++) {
            const uint32_t kb = kh * 32;
            uint32_t ah[4][4], al[4][4];
#pragma unroll
            for (int mi = 0; mi < 4; mi++) {
                ldsm4(ah[mi], aAh + mi * (16 * SROW * 2) + kb);
                ldsm4(al[mi], aAl + mi * (16 * SROW * 2) + kb);
            }
#pragma unroll
            for (int np = 0; np < 2; np++) {
                uint32_t bh2[4];
                ldsm4(bh2, aBh + np * (16 * SROW * 2) + kb);
#pragma unroll
                for (int mi = 0; mi < 4; mi++) {
                    mma16816h(acc[mi][2 * np],     ah[mi], bh2);
                    mma16816h(acc[mi][2 * np],     al[mi], bh2);
                    mma16816h(acc[mi][2 * np + 1], ah[mi], bh2 + 2);
                    mma16816h(acc[mi][2 * np + 1], al[mi], bh2 + 2);
                }
            }
        }
        __syncthreads();
    }

    const int col0 = bn + warp_n * 32 + (lane & 3) * 2;
    const int row0 = bm + warp_m * 64 + (lane >> 2);
#pragma unroll
    for (int mi = 0; mi < 4; mi++) {
#pragma unroll
        for (int half = 0; half < 2; half++) {
            const int m = row0 + mi * 16 + half * 8;
            if (m >= M_ROWS) continue;
            size_t crow;
            if (MODE == 0) crow = (size_t)m * NOUT;
            else           crow = (size_t)((m % SEQ) * BATCH + (m / SEQ)) * NOUT;
#pragma unroll
            for (int nj = 0; nj < 4; nj++) {
                const int col = col0 + nj * 8;
                float2 o = make_float2(acc[mi][nj][2 * half], acc[mi][nj][2 * half + 1]);
                if (MODE == 1) {
                    float2 bv = *(const float2*)&bias[col];
                    o.x += bv.x; o.y += bv.y;
                }
                *(float2*)&C[crow + col] = o;
            }
        }
    }
}

// ============================================================================
// prep (norm fused): per (bh,row) write FP16 of vn = v*inv and of raw v;
// zero-pad rows >= SEQ.
// ============================================================================
__global__ void prep_kernel(const float* __restrict__ v,
                            __half* __restrict__ vnh, __half* __restrict__ vh_)
{
    int idx = blockIdx.x * blockDim.x + threadIdx.x;
    if (idx >= BHN * NKP) return;
    const int bh = idx / NKP, row = idx % NKP;
    const int b = bh / NH, h = bh % NH;
    const size_t dst = (size_t)idx * HD;
    if (row < SEQ) {
        const float* src = v + (size_t)(b * SEQ + row) * DIM + h * HD;
        float4 vbuf[16];
        float acc = 0.f;
#pragma unroll
        for (int c = 0; c < 16; c++) {
            float4 t = *(const float4*)(src + 4 * c);
            vbuf[c] = t;
            acc += t.x * t.x + t.y * t.y + t.z * t.z + t.w * t.w;
        }
        const float iv = 1.f / fmaxf(sqrtf(acc), 1e-6f);
#pragma unroll 4
        for (int c = 0; c < 16; c++) {
            float vv[4] = {vbuf[c].x, vbuf[c].y, vbuf[c].z, vbuf[c].w};
            union { __half b[4]; uint2 u; } nh, rh;
#pragma unroll
            for (int j = 0; j < 4; j++) {
                nh.b[j] = __float2half_rn(vv[j] * iv);
                rh.b[j] = __float2half_rn(vv[j]);
            }
            *(uint2*)(vnh + dst + 4 * c) = nh.u;
            *(uint2*)(vh_ + dst + 4 * c) = rh.u;
        }
    } else {
        uint2 z = {0, 0};
#pragma unroll 4
        for (int c = 0; c < HD; c += 4) {
            *(uint2*)(vnh + dst + c) = z;
            *(uint2*)(vh_ + dst + c) = z;
        }
    }
}

// ============================================================================
// row0 stage A: per (b,h) u = Wk^T (0.125 * Wq x0), exact fp32. 96 blocks.
// ============================================================================
__global__ __launch_bounds__(256) void u_kernel(const float* __restrict__ x,
                                                const float* __restrict__ w_qkv,
                                                float* __restrict__ u_out)
{
    __shared__ float q0s[HD];
    const int tid = threadIdx.x;
    const int lane = tid & 31, wid = tid >> 5;
    const int b = blockIdx.x / NH, h = blockIdx.x % NH;

    {
        const float4* xr4 = (const float4*)(x + (size_t)b * DIM);
#pragma unroll 1
        for (int i = 0; i < 8; i++) {
            const int d = wid * 8 + i;
            const float4* wrow = (const float4*)(w_qkv + (size_t)(h * HD + d) * DIM);
            float acc = 0.f;
#pragma unroll
            for (int c = lane; c < DIM / 4; c += 32) {
                float4 wv = wrow[c];
                float4 xv = xr4[c];
                acc += wv.x * xv.x + wv.y * xv.y + wv.z * xv.z + wv.w * xv.w;
            }
            acc = warp_sum(acc);
            if (lane == 0) q0s[d] = 0.125f * acc;
        }
    }
    __syncthreads();

    const float* wk = w_qkv + ((size_t)DIM + h * HD) * DIM;
    float* uo = u_out + (size_t)blockIdx.x * DIM;
    for (int k = tid; k < DIM; k += 256) {
        float acc = 0.f;
#pragma unroll 8
        for (int dd = 0; dd < HD; dd++)
            acc += q0s[dd] * wk[(size_t)dd * DIM + k];
        uo[k] = acc;
    }
}

// ============================================================================
// row0 stage B: scores for all 12 heads at once; x read once per batch-tile.
// ============================================================================
__global__ __launch_bounds__(256) void score_kernel(const float* __restrict__ x,
                                                    const float* __restrict__ u_in,
                                                    float* __restrict__ sc_out)
{
    __shared__ float sU[NH * DIM];   // 36 KB
    const int tid = threadIdx.x;
    const int lane = tid & 31, wid = tid >> 5;
    const int tile = blockIdx.x, b = blockIdx.y;

    for (int i = tid; i < NH * DIM; i += 256)
        sU[i] = u_in[(size_t)b * NH * DIM + i];
    __syncthreads();

    const int j0 = tile * 128 + wid * 16;
#pragma unroll 1
    for (int r = 0; r < 16; r++) {
        const int j = j0 + r;
        if (j >= SEQ) break;
        const float4* xr = (const float4*)(x + (size_t)(j * BATCH + b) * DIM);
        float acc[NH];
#pragma unroll
        for (int h = 0; h < NH; h++) acc[h] = 0.f;
#pragma unroll 1
        for (int c = lane; c < DIM / 4; c += 32) {
            float4 xv = xr[c];
#pragma unroll
            for (int h = 0; h < NH; h++) {
                float4 uv = ((const float4*)(sU + h * DIM))[c];
                acc[h] += uv.x * xv.x + uv.y * xv.y + uv.z * xv.z + uv.w * xv.w;
            }
        }
#pragma unroll
        for (int h = 0; h < NH; h++) acc[h] = warp_sum(acc[h]);
        if (lane == 0) {
#pragma unroll
            for (int h = 0; h < NH; h++)
                sc_out[(size_t)(b * NH + h) * SEQ + j] = acc[h];
        }
    }
}

// ============================================================================
// row0 stage C: per (b,h) softmax + PV from g_v; writes fp16 hi/lo output.
// ============================================================================
__global__ __launch_bounds__(256) void softpv_kernel(const float* __restrict__ sc_in,
                                                     const float* __restrict__ v,
                                                     __half* __restrict__ ohi,
                                                     __half* __restrict__ olo)
{
    __shared__ float sc[SEQ];
    __shared__ float red[256];
    __shared__ float part[4][HD];
    const int tid = threadIdx.x;
    const int b = blockIdx.x / NH, h = blockIdx.x % NH;

    for (int j = tid; j < SEQ; j += 256)
        sc[j] = sc_in[(size_t)blockIdx.x * SEQ + j];
    __syncthreads();

    float lmax = -1e30f;
    for (int j = tid; j < SEQ; j += 256) lmax = fmaxf(lmax, sc[j]);
    red[tid] = lmax; __syncthreads();
    for (int s = 128; s > 0; s >>= 1) {
        if (tid < s) red[tid] = fmaxf(red[tid], red[tid + s]);
        __syncthreads();
    }
    float mval = red[0];
    __syncthreads();

    float lsum = 0.f;
    for (int j = tid; j < SEQ; j += 256) {
        float p = __expf(sc[j] - mval);
        sc[j] = p;
        lsum += p;
    }
    red[tid] = lsum; __syncthreads();
    for (int s = 128; s > 0; s >>= 1) {
        if (tid < s) red[tid] += red[tid + s];
        __syncthreads();
    }
    float l = red[0];
    __syncthreads();

    const int d = tid & 63, pi = tid >> 6;
    float acc = 0.f;
    const float* vbase = v + (size_t)(b * SEQ) * DIM + h * HD;
    for (int j = pi; j < SEQ; j += 4)
        acc += sc[j] * vbase[(size_t)j * DIM + d];
    part[pi][d] = acc;
    __syncthreads();
    if (tid < HD) {
        float s = (part[0][tid] + part[1][tid] + part[2][tid] + part[3][tid]) / l;
        const size_t o = (size_t)(b * SEQ) * DIM + h * HD + tid;
        __half hh = __float2half_rn(s);
        ohi[o] = hh;
        olo[o] = __float2half_rn(s - __half2float(hh));
    }
}

// ============================================================================
// Fused FA2-style VV attention (FP16), rows 1..1024, cp.async double-buffered.
// S = Q·K (1-pass fp16); PV = P·V (1-pass fp16). fp16 hi/lo output.
// ============================================================================
#define VVT (2 * 128 * SROW2)             /* fp16 elems per stage (K,V) */
#define VV_SMEM (2 * VVT * 2)             /* 73728 bytes */

__global__ __launch_bounds__(256, 1)
void vv_mma_kernel(const __half* __restrict__ vnh, const __half* __restrict__ vvh,
                   __half* __restrict__ ohi, __half* __restrict__ olo)
{
    extern __shared__ __half smh[];
    const uint32_t smB = smem_u32(smh);

    const int tid = threadIdx.x, lane = tid & 31, wid = tid >> 5;
    const int bh = blockIdx.y, qt = blockIdx.x;
    const int b = bh / NH, h = bh % NH;
    const int q0 = 1 + qt * 128;
    const size_t base = (size_t)bh * NKP * HD;

    const int ld_r = tid >> 1, ld_c = (tid & 1) * 32;
    const uint32_t ld_sm = (uint32_t)(ld_r * SROW2 + ld_c) * 2;
    const size_t   ld_g0 = (size_t)ld_r * HD + ld_c;

#define SK(s)  (smB + (uint32_t)(s) * (VVT * 2))
#define SVH(s) (SK(s) + 128 * SROW2 * 2)

#define VV_ISSUE(s, kt)                                                        \
    do {                                                                       \
        const size_t g = base + (size_t)(kt) * 128 * HD + ld_g0;               \
        const uint32_t dK = SK(s) + ld_sm, dH = SVH(s) + ld_sm;                \
        cp16(dK + 0,  vnh + g,      true); cp16(dK + 16, vnh + g + 8,  true);  \
        cp16(dK + 32, vnh + g + 16, true); cp16(dK + 48, vnh + g + 24, true);  \
        cp16(dH + 0,  vvh + g,      true); cp16(dH + 16, vvh + g + 8,  true);  \
        cp16(dH + 32, vvh + g + 16, true); cp16(dH + 48, vvh + g + 24, true);  \
        CP_COMMIT();                                                           \
    } while (0)

    VV_ISSUE(0, 0);

    // stage Q into stage-1 K buffer via regular loads; extract fragments
    {
        const size_t g = base + (size_t)(q0 + ld_r) * HD + ld_c;
        uint4* dh = (uint4*)((char*)smh + (VVT * 2) + (ld_r * SROW2 + ld_c) * 2);
        const uint4* p1 = (const uint4*)(vnh + g);
#pragma unroll
        for (int i = 0; i < 4; i++) dh[i] = p1[i];
    }
    __syncthreads();
    uint32_t qh[4][4];
    {
        const int a_r = wid * 16 + (lane & 7) + ((lane >> 3) & 1) * 8;
        const int a_k = (lane >> 4) * 8;
        const uint32_t ah = SK(1) + (uint32_t)(a_r * SROW2 + a_k) * 2;
#pragma unroll
        for (int kt = 0; kt < 4; kt++)
            ldsm4(qh[kt], ah + kt * 16 * 2);
    }

    float oacc[8][4];
#pragma unroll
    for (int g = 0; g < 8; g++)
#pragma unroll
        for (int r = 0; r < 4; r++) oacc[g][r] = 0.f;
    float la = 0.f, lb = 0.f;

    const int b_n = (lane & 7) + (lane >> 4) * 8;
    const int b_k = ((lane >> 3) & 1) * 8;
    const int t_r = lane & 15, t_c = (lane >> 4) * 8;

#pragma unroll 1
    for (int ktile = 0; ktile < 9; ktile++) {
        const int st = ktile & 1;
        CP_WAIT0();
        __syncthreads();
        if (ktile < 8) VV_ISSUE(st ^ 1, ktile + 1);

        const uint32_t sKh_u = SK(st), sVh_u = SVH(st);

        // scores: 1-pass fp16 Q x K
        float p[16][4];
#pragma unroll
        for (int f = 0; f < 16; f++)
#pragma unroll
            for (int r = 0; r < 4; r++) p[f][r] = 0.f;

#pragma unroll
        for (int kt = 0; kt < 4; kt++) {
#pragma unroll
            for (int g = 0; g < 8; g++) {
                uint32_t kh_[4];
                const uint32_t off = (uint32_t)((g * 16 + b_n) * SROW2 + kt * 16 + b_k) * 2;
                ldsm4(kh_, sKh_u + off);
                mma16816h(p[2*g],   qh[kt], kh_);
                mma16816h(p[2*g+1], qh[kt], kh_ + 2);
            }
        }

        // softmax probs (fixed max), accumulate l (fp32)
#pragma unroll
        for (int f = 0; f < 16; f++) {
            float2 e0 = exp_poly2(make_float2(p[f][0], p[f][1]));
            float2 e1 = exp_poly2(make_float2(p[f][2], p[f][3]));
            p[f][0] = e0.x; p[f][1] = e0.y; p[f][2] = e1.x; p[f][3] = e1.y;
            la += e0.x + e0.y;
            lb += e1.x + e1.y;
        }

        // PV: 1-pass fp16 P x V
#pragma unroll
        for (int kt = 0; kt < 8; kt++) {
            uint32_t pah[4];
            {
                const float* sA = p[2 * kt];
                const float* sB = p[2 * kt + 1];
                pah[0] = pack_f16x2(sA[0], sA[1]);
                pah[1] = pack_f16x2(sA[2], sA[3]);
                pah[2] = pack_f16x2(sB[0], sB[1]);
                pah[3] = pack_f16x2(sB[2], sB[3]);
            }
#pragma unroll
            for (int g = 0; g < 4; g++) {
                uint32_t vh_[4];
                const uint32_t off = (uint32_t)((kt * 16 + t_r) * SROW2 + g * 16 + t_c) * 2;
                ldsm4t(vh_, sVh_u + off);
                mma16816h(oacc[2*g],   pah, vh_);
                mma16816h(oacc[2*g+1], pah, vh_ + 2);
            }
        }
    }

    // l reduce + pad correction + fp16 hi/lo output
    la += __shfl_xor_sync(0xffffffffu, la, 1);
    la += __shfl_xor_sync(0xffffffffu, la, 2);
    lb += __shfl_xor_sync(0xffffffffu, lb, 1);
    lb += __shfl_xor_sync(0xffffffffu, lb, 2);
    float P0;
    {
        float t = -0.125f;
        float hh = fmaf(t, 1.f/24.f, 1.f/6.f);
        hh = fmaf(t, hh, 0.5f);
        hh = fmaf(t, hh, 1.f);
        hh = fmaf(t, hh, 1.f);
        P0 = hh;
    }
    la -= 127.f * P0;
    lb -= 127.f * P0;
    const float ia = 1.f / la, ib = 1.f / lb;

    const int row_a = q0 + wid * 16 + (lane >> 2);
    const int col0 = h * HD + (lane & 3) * 2;
    const size_t oa = (size_t)(b * SEQ + row_a) * DIM;
    const size_t ob = (size_t)(b * SEQ + row_a + 8) * DIM;
#pragma unroll
    for (int g = 0; g < 8; g++) {
        float x0 = oacc[g][0] * ia, x1 = oacc[g][1] * ia;
        float y0 = oacc[g][2] * ib, y1 = oacc[g][3] * ib;
        uint32_t xh = pack_f16x2(x0, x1);
        uint32_t yh = pack_f16x2(y0, y1);
        float2 fxh = unpack_f16x2(xh);
        float2 fyh = unpack_f16x2(yh);
        uint32_t xl = pack_f16x2(x0 - fxh.x, x1 - fxh.y);
        uint32_t yl = pack_f16x2(y0 - fyh.x, y1 - fyh.y);
        *(uint32_t*)(ohi + oa + col0 + g * 8) = xh;
        *(uint32_t*)(olo + oa + col0 + g * 8) = xl;
        *(uint32_t*)(ohi + ob + col0 + g * 8) = yh;
        *(uint32_t*)(olo + ob + col0 + g * 8) = yl;
    }
}

// ============================================================================
extern "C" void kernel_launch(void* const* d_in, const int* in_sizes, int n_in,
                              void* d_out, int out_size)
{
    const float* x      = (const float*)d_in[0];
    const float* w_qkv  = (const float*)d_in[1];
    const float* w_proj = (const float*)d_in[2];
    const float* b_proj = (const float*)d_in[3];
    float* out = (float*)d_out;

    float *p_v, *p_u, *p_sc;
    cudaGetSymbolAddress((void**)&p_v,  g_v);
    cudaGetSymbolAddress((void**)&p_u,  g_u);
    cudaGetSymbolAddress((void**)&p_sc, g_sc);
    __half *p_xh, *p_xl, *p_wv, *p_oh, *p_ol, *p_wp, *p_vnh, *p_vhh;
    cudaGetSymbolAddress((void**)&p_xh,  g_xh);
    cudaGetSymbolAddress((void**)&p_xl,  g_xl);
    cudaGetSymbolAddress((void**)&p_wv,  g_wv);
    cudaGetSymbolAddress((void**)&p_oh,  g_oh);
    cudaGetSymbolAddress((void**)&p_ol,  g_ol);
    cudaGetSymbolAddress((void**)&p_wp,  g_wp);
    cudaGetSymbolAddress((void**)&p_vnh, g_vn_h);
    cudaGetSymbolAddress((void**)&p_vhh, g_v_h);

    cudaFuncSetAttribute(vv_mma_kernel, cudaFuncAttributeMaxDynamicSharedMemorySize, VV_SMEM);
    cudaFuncSetAttribute(mma_gemm<0, DIM>, cudaFuncAttributeMaxDynamicSharedMemorySize, GEMM_SMEM);
    cudaFuncSetAttribute(mma_gemm<1, DIM>, cudaFuncAttributeMaxDynamicSharedMemorySize, GEMM_SMEM);

    // 0) conversions: x -> fp16 hi/lo; v-weights, proj-weights -> fp16
    {
        int n4x = M_ROWS * DIM / 4;
        cvt_hl_kernel<<<(n4x + 255) / 256, 256>>>(x, p_xh, p_xl, n4x);
        int n4w = DIM * DIM / 4;
        cvt_h_kernel<<<(n4w + 255) / 256, 256>>>(w_qkv + (size_t)2 * DIM * DIM, p_wv, n4w);
        cvt_h_kernel<<<(n4w + 255) / 256, 256>>>(w_proj, p_wp, n4w);
    }
    // 1) V GEMM (fp16 2-pass) -> g_v
    {
        dim3 grid(DIM / 128, (M_ROWS + 127) / 128);
        mma_gemm<0, DIM><<<grid, 256, GEMM_SMEM>>>(p_xh, p_xl, p_wv, nullptr, p_v);
    }
    // 2) prep (norm fused): vn/v fp16 padded operands
    {
        int total = BHN * NKP;
        prep_kernel<<<(total + 255) / 256, 256>>>(p_v, p_vnh, p_vhh);
    }
    // 3) row0: u vectors, batched scores, softmax+PV
    u_kernel<<<BHN, 256>>>(x, w_qkv, p_u);
    {
        dim3 grid(9, BATCH);
        score_kernel<<<grid, 256>>>(x, p_u, p_sc);
    }
    softpv_kernel<<<BHN, 256>>>(p_sc, p_v, p_oh, p_ol);
    // 4) VV cosine attention rows 1..1024 (fp16)
    {
        dim3 grid(8, BHN);
        vv_mma_kernel<<<grid, 256, VV_SMEM>>>(p_vnh, p_vhh, p_oh, p_ol);
    }
    // 5) proj GEMM (fp16 2-pass) + bias -> out
    {
        dim3 grid(DIM / 128, (M_ROWS + 127) / 128);
        mma_gemm<1, DIM><<<grid, 256, GEMM_SMEM>>>(p_oh, p_ol, p_wp, b_proj, out);
    }
}